// round 7
// baseline (speedup 1.0000x reference)
#include <cuda_runtime.h>
#include <cuda_bf16.h>
#include <cstdint>
#include <math.h>

#define TSEQ 2048
#define NE   1024
#define NH   16
#define DKH  64
#define NB   2
#define MTOT (NB*TSEQ)   // 4096

// Pre-split scratch (allocation-free): hi/lo bf16 pairs.
__device__ __nv_bfloat16 g_Xh[MTOT*NE], g_Xl[MTOT*NE];
__device__ __nv_bfloat16 g_Wh[4*NE*NE], g_Wl[4*NE*NE];      // q,k,v,o
__device__ __nv_bfloat16 g_Qh[MTOT*NE], g_Ql[MTOT*NE];
__device__ __nv_bfloat16 g_Kh[MTOT*NE], g_Kl[MTOT*NE];
__device__ __nv_bfloat16 g_Vh[MTOT*NE], g_Vl[MTOT*NE];
__device__ __nv_bfloat16 g_Yh[MTOT*NE], g_Yl[MTOT*NE];

// ---------------------------------------------------------------------------
// Baseline-PTX tensor ops + cp.async (plain sm_103 target)
// ---------------------------------------------------------------------------
static __device__ __forceinline__ uint32_t smem_u32(const void* p) {
    uint32_t a;
    asm("{ .reg .u64 t; cvta.to.shared.u64 t, %1; cvt.u32.u64 %0, t; }" : "=r"(a) : "l"(p));
    return a;
}
static __device__ __forceinline__ void ldsm_x4(uint32_t& r0, uint32_t& r1,
                                               uint32_t& r2, uint32_t& r3, uint32_t a) {
    asm volatile("ldmatrix.sync.aligned.m8n8.x4.shared.b16 {%0,%1,%2,%3}, [%4];"
                 : "=r"(r0), "=r"(r1), "=r"(r2), "=r"(r3) : "r"(a));
}
static __device__ __forceinline__ void ldsm_x4_t(uint32_t& r0, uint32_t& r1,
                                                 uint32_t& r2, uint32_t& r3, uint32_t a) {
    asm volatile("ldmatrix.sync.aligned.m8n8.x4.trans.shared.b16 {%0,%1,%2,%3}, [%4];"
                 : "=r"(r0), "=r"(r1), "=r"(r2), "=r"(r3) : "r"(a));
}
static __device__ __forceinline__ void mma16816(float* c, const uint32_t* a, const uint32_t* b) {
    asm volatile("mma.sync.aligned.m16n8k16.row.col.f32.bf16.bf16.f32 "
                 "{%0,%1,%2,%3}, {%4,%5,%6,%7}, {%8,%9}, {%0,%1,%2,%3};"
                 : "+f"(c[0]), "+f"(c[1]), "+f"(c[2]), "+f"(c[3])
                 : "r"(a[0]), "r"(a[1]), "r"(a[2]), "r"(a[3]), "r"(b[0]), "r"(b[1]));
}
#define CP_A16(dst, src) asm volatile("cp.async.cg.shared.global [%0], [%1], 16;" :: "r"(dst), "l"(src))
#define CP_COMMIT()      asm volatile("cp.async.commit_group;" ::: "memory")
#define CP_WAIT0()       asm volatile("cp.async.wait_group 0;" ::: "memory")
#define CP_WAIT1()       asm volatile("cp.async.wait_group 1;" ::: "memory")
#define CP_WAIT2()       asm volatile("cp.async.wait_group 2;" ::: "memory")

// Split fp32 quad -> hi/lo bf16 quads, store 8B each.
static __device__ __forceinline__ void split_store(char* hi, char* lo, float4 v) {
    __nv_bfloat16 hx = __float2bfloat16_rn(v.x), hy = __float2bfloat16_rn(v.y);
    __nv_bfloat16 hz = __float2bfloat16_rn(v.z), hw = __float2bfloat16_rn(v.w);
    union { __nv_bfloat162 h[2]; uint2 u; } p;
    p.h[0].x = hx; p.h[0].y = hy; p.h[1].x = hz; p.h[1].y = hw;
    *(uint2*)hi = p.u;
    p.h[0].x = __float2bfloat16_rn(v.x - __bfloat162float(hx));
    p.h[0].y = __float2bfloat16_rn(v.y - __bfloat162float(hy));
    p.h[1].x = __float2bfloat16_rn(v.z - __bfloat162float(hz));
    p.h[1].y = __float2bfloat16_rn(v.w - __bfloat162float(hw));
    *(uint2*)lo = p.u;
}
static __device__ __forceinline__ void pack_split(float x, float y, uint32_t& h, uint32_t& l) {
    union { __nv_bfloat162 b; uint32_t u; } ph, pl;
    __nv_bfloat16 hx = __float2bfloat16_rn(x), hy = __float2bfloat16_rn(y);
    ph.b.x = hx; ph.b.y = hy;
    pl.b.x = __float2bfloat16_rn(x - __bfloat162float(hx));
    pl.b.y = __float2bfloat16_rn(y - __bfloat162float(hy));
    h = ph.u; l = pl.u;
}

// ---------------------------------------------------------------------------
// Pre-pass: split one fp32 array into hi/lo bf16. n must be multiple of 1024.
// ---------------------------------------------------------------------------
__global__ void split_one(const float* __restrict__ src,
                          __nv_bfloat16* __restrict__ hi, __nv_bfloat16* __restrict__ lo)
{
    size_t i = ((size_t)blockIdx.x * 256 + threadIdx.x) * 4;
    float4 v = *(const float4*)(src + i);
    split_store((char*)(hi + i), (char*)(lo + i), v);
}

// ---------------------------------------------------------------------------
// GEMM on pre-split operands: C = A * W^T (+bias)(*scale). 128x128 tile,
// kc=32, 4-stage cp.async ring. MODE 0: split-bf16 out (QKV); MODE 1: fp32.
// ---------------------------------------------------------------------------
#define GSTRIDE 80
#define GTILE   (128 * GSTRIDE)       // 10240
#define GSTAGE  (4 * GTILE)           // 40960 : Ah|Al|Wh|Wl
#define GSMEM   (4 * GSTAGE)          // 163840
#define NKC     (NE / 32)             // 32

template<int MODE>
__global__ void __launch_bounds__(256)
gemm_s(const __nv_bfloat16* __restrict__ Ah, const __nv_bfloat16* __restrict__ Al,
       const __nv_bfloat16* __restrict__ WhB, const __nv_bfloat16* __restrict__ WlB,
       const float* __restrict__ b0, const float* __restrict__ b1, const float* __restrict__ b2,
       __nv_bfloat16* __restrict__ O0h, __nv_bfloat16* __restrict__ O0l,
       __nv_bfloat16* __restrict__ O1h, __nv_bfloat16* __restrict__ O1l,
       __nv_bfloat16* __restrict__ O2h, __nv_bfloat16* __restrict__ O2l,
       float* __restrict__ Fout)
{
    extern __shared__ char smem[];
    const int tid  = threadIdx.x;
    const int wid  = tid >> 5;
    const int lane = tid & 31;
    const int z    = blockIdx.z;
    const __nv_bfloat16* Wh = WhB + (size_t)z * NE * NE;
    const __nv_bfloat16* Wl = WlB + (size_t)z * NE * NE;
    const float* bias = (z == 0) ? b0 : (z == 1) ? b1 : b2;
    const int mbase = blockIdx.y * 128;
    const int nbase = blockIdx.x * 128;
    const uint32_t smb = smem_u32(smem);

    const int warp_m = wid >> 2;
    const int warp_n = wid & 3;
    const int la_row = warp_m * 64 + (lane & 15);
    const int la_k8  = ((lane >> 4) & 1) * 8;
    const int lw_row = warp_n * 32 + (lane & 7) + ((lane >> 4) & 1) * 8;
    const int lw_k8  = ((lane >> 3) & 1) * 8;

    // loader: thread -> rows lr, lr+64; 16B chunk lc per tile.
    const int lr = tid >> 2;       // 0..63
    const int lc = tid & 3;        // 0..3

    float acc[4][4][4];
#pragma unroll
    for (int mi = 0; mi < 4; mi++)
#pragma unroll
        for (int nf = 0; nf < 4; nf++)
#pragma unroll
            for (int q = 0; q < 4; q++) acc[mi][nf][q] = 0.f;

    const __nv_bfloat16* gptr[4] = { Ah, Al, Wh, Wl };

#define LOAD_STAGE(buf, kt) do {                                              \
        uint32_t sb_ = smb + (buf) * GSTAGE;                                  \
        int kcol_ = (kt) * 32 + lc * 8;                                       \
        _Pragma("unroll")                                                     \
        for (int t4 = 0; t4 < 4; t4++) {                                      \
            int rb_ = (t4 < 2) ? mbase : nbase;                               \
            _Pragma("unroll")                                                 \
            for (int hf = 0; hf < 2; hf++) {                                  \
                int r_ = lr + hf * 64;                                        \
                const char* src_ = (const char*)(gptr[t4] +                   \
                    (size_t)(rb_ + r_) * NE + kcol_);                         \
                CP_A16(sb_ + t4 * GTILE + r_ * GSTRIDE + lc * 16, src_);      \
            }                                                                 \
        }                                                                     \
    } while (0)

    LOAD_STAGE(0, 0); CP_COMMIT();
    LOAD_STAGE(1, 1); CP_COMMIT();
    LOAD_STAGE(2, 2); CP_COMMIT();

    for (int kt = 0; kt < NKC; kt++) {
        if (kt <= NKC - 3)      CP_WAIT2();
        else if (kt == NKC - 2) CP_WAIT1();
        else                    CP_WAIT0();
        __syncthreads();
        if (kt + 3 < NKC) { LOAD_STAGE((kt + 3) & 3, kt + 3); CP_COMMIT(); }

        const uint32_t base = smb + (kt & 3) * GSTAGE;
#pragma unroll
        for (int ks = 0; ks < 2; ks++) {
            uint32_t ah[4][4], al[4][4];
#pragma unroll
            for (int mi = 0; mi < 4; mi++) {
                uint32_t aoff = (uint32_t)(la_row + mi*16) * GSTRIDE + (ks*16 + la_k8) * 2;
                ldsm_x4(ah[mi][0], ah[mi][1], ah[mi][2], ah[mi][3], base + aoff);
                ldsm_x4(al[mi][0], al[mi][1], al[mi][2], al[mi][3], base + GTILE + aoff);
            }
            uint32_t wh[2][4], wl[2][4];
#pragma unroll
            for (int nj = 0; nj < 2; nj++) {
                uint32_t woff = (uint32_t)(lw_row + nj*16) * GSTRIDE + (ks*16 + lw_k8) * 2;
                ldsm_x4(wh[nj][0], wh[nj][1], wh[nj][2], wh[nj][3], base + 2*GTILE + woff);
                ldsm_x4(wl[nj][0], wl[nj][1], wl[nj][2], wl[nj][3], base + 3*GTILE + woff);
            }
#pragma unroll
            for (int mi = 0; mi < 4; mi++)
#pragma unroll
                for (int nf = 0; nf < 4; nf++) {
                    const uint32_t* bh = &wh[nf >> 1][(nf & 1) * 2];
                    const uint32_t* bl = &wl[nf >> 1][(nf & 1) * 2];
                    mma16816(acc[mi][nf], ah[mi], bh);
                    mma16816(acc[mi][nf], ah[mi], bl);
                    mma16816(acc[mi][nf], al[mi], bh);
                }
        }
    }

    // epilogue
    const int crow  = mbase + warp_m * 64 + (lane >> 2);
    const int ccol0 = nbase + warp_n * 32 + (lane & 3) * 2;
    if constexpr (MODE == 0) {
        __nv_bfloat16* Oh = (z == 0) ? O0h : (z == 1) ? O1h : O2h;
        __nv_bfloat16* Ol = (z == 0) ? O0l : (z == 1) ? O1l : O2l;
        const float scale = (z == 0) ? 0.125f : 1.0f;
#pragma unroll
        for (int nf = 0; nf < 4; nf++) {
            float2 bv = *(const float2*)(bias + ccol0 + nf * 8);
#pragma unroll
            for (int mi = 0; mi < 4; mi++) {
                float* c = acc[mi][nf];
                uint32_t h0, l0, h1, l1;
                pack_split((c[0] + bv.x) * scale, (c[1] + bv.y) * scale, h0, l0);
                pack_split((c[2] + bv.x) * scale, (c[3] + bv.y) * scale, h1, l1);
                size_t o0 = (size_t)(crow + mi*16)     * NE + ccol0 + nf*8;
                size_t o1 = (size_t)(crow + mi*16 + 8) * NE + ccol0 + nf*8;
                *(uint32_t*)(Oh + o0) = h0; *(uint32_t*)(Ol + o0) = l0;
                *(uint32_t*)(Oh + o1) = h1; *(uint32_t*)(Ol + o1) = l1;
            }
        }
    } else {
#pragma unroll
        for (int nf = 0; nf < 4; nf++) {
            float2 bv = *(const float2*)(bias + ccol0 + nf * 8);
#pragma unroll
            for (int mi = 0; mi < 4; mi++) {
                float* c = acc[mi][nf];
                *(float2*)(Fout + (size_t)(crow + mi*16)     * NE + ccol0 + nf*8) =
                    make_float2(c[0] + bv.x, c[1] + bv.y);
                *(float2*)(Fout + (size_t)(crow + mi*16 + 8) * NE + ccol0 + nf*8) =
                    make_float2(c[2] + bv.x, c[3] + bv.y);
            }
        }
    }
#undef LOAD_STAGE
}

// ---------------------------------------------------------------------------
// Tensorized flash attention on pre-split Q/K/V; 2-stage cp.async K/V ring.
// CTA: 64 q-rows, 4 warps. Row stride 144B (64 bf16 + pad), conflict-free.
// ---------------------------------------------------------------------------
#define ARSTRIDE 144
#define ATILE    (64 * ARSTRIDE)       // 9216
#define ASTAGE   (4 * ATILE)           // 36864 : Kh|Kl|Vh|Vl
#define ASMEM2   (2 * ASTAGE)          // 73728

__global__ void __launch_bounds__(128, 3)
attn_tc()
{
    extern __shared__ char smem[];
    const int tid  = threadIdx.x;
    const int wid  = tid >> 5;
    const int lane = tid & 31;
    const int qt   = (int)gridDim.x - 1 - (int)blockIdx.x;   // heavy first
    const int bh   = blockIdx.y;
    const int b    = bh >> 4;
    const int h    = bh & 15;
    const size_t base = (size_t)b * TSEQ * NE + (size_t)h * DKH;
    const int qb   = qt * 64;
    const uint32_t smb = smem_u32(smem);

    // ---- stage Q (hi/lo) through buf0, grab fragments ----
#pragma unroll
    for (int i = 0; i < 4; i++) {
        int idx = i * 128 + tid;
        int r = idx >> 3, c = idx & 7;
        uint4 vh = *(const uint4*)(g_Qh + base + (size_t)(qb + r) * NE + c * 8);
        uint4 vl = *(const uint4*)(g_Ql + base + (size_t)(qb + r) * NE + c * 8);
        *(uint4*)(smem + r * ARSTRIDE + c * 16)         = vh;
        *(uint4*)(smem + ATILE + r * ARSTRIDE + c * 16) = vl;
    }
    __syncthreads();

    const int la_row = wid * 16 + (lane & 15);
    const int la_k8  = ((lane >> 4) & 1) * 8;
    uint32_t qh[4][4], ql[4][4];
#pragma unroll
    for (int ks = 0; ks < 4; ks++) {
        uint32_t aoff = (uint32_t)la_row * ARSTRIDE + (ks * 16 + la_k8) * 2;
        ldsm_x4(qh[ks][0], qh[ks][1], qh[ks][2], qh[ks][3], smb + aoff);
        ldsm_x4(ql[ks][0], ql[ks][1], ql[ks][2], ql[ks][3], smb + ATILE + aoff);
    }
    __syncthreads();   // buf0 about to be overwritten by K/V prefetch

    const int lw_row = (lane & 7) + ((lane >> 4) & 1) * 8;
    const int lw_k8  = ((lane >> 3) & 1) * 8;
    const int vt_row = (lane & 7) + ((lane >> 3) & 1) * 8;
    const int vt_cb  = ((lane >> 4) & 1) * 16;

    float m_r[2] = {-1e30f, -1e30f}, l_r[2] = {0.f, 0.f};
    float o[8][4];
#pragma unroll
    for (int nf = 0; nf < 8; nf++)
#pragma unroll
        for (int q = 0; q < 4; q++) o[nf][q] = 0.f;

    const __nv_bfloat16* kvp[4] = { g_Kh, g_Kl, g_Vh, g_Vl };

#define LOAD_KV(buf, kt) do {                                                 \
        uint32_t sb_ = smb + (buf) * ASTAGE;                                  \
        int ktb_ = (kt) * 64;                                                 \
        _Pragma("unroll")                                                     \
        for (int i = 0; i < 16; i++) {                                        \
            int id_ = i * 128 + tid;                                          \
            int t4_ = id_ >> 9;                                               \
            int ix_ = id_ & 511;                                              \
            int r_ = ix_ >> 3, c_ = ix_ & 7;                                  \
            const char* src_ = (const char*)(kvp[t4_] + base +                \
                (size_t)(ktb_ + r_) * NE + c_ * 8);                           \
            CP_A16(sb_ + t4_ * ATILE + r_ * ARSTRIDE + c_ * 16, src_);        \
        }                                                                     \
    } while (0)

    const int nkt = qt + 1;
    LOAD_KV(0, 0); CP_COMMIT();
    if (nkt > 1) { LOAD_KV(1, 1); CP_COMMIT(); }

    for (int kt = 0; kt < nkt; kt++) {
        if (kt + 1 < nkt) CP_WAIT1(); else CP_WAIT0();
        __syncthreads();
        const uint32_t sb = smb + (kt & 1) * ASTAGE;

        // ---- S = Q K^T ----
        float s[8][4];
#pragma unroll
        for (int nf = 0; nf < 8; nf++)
#pragma unroll
            for (int q = 0; q < 4; q++) s[nf][q] = 0.f;

#pragma unroll
        for (int ks = 0; ks < 4; ks++) {
            uint32_t kh[4][4], kl[4][4];
#pragma unroll
            for (int nj = 0; nj < 4; nj++) {
                uint32_t woff = (uint32_t)(nj * 16 + lw_row) * ARSTRIDE + (ks * 16 + lw_k8) * 2;
                ldsm_x4(kh[nj][0], kh[nj][1], kh[nj][2], kh[nj][3], sb + woff);
                ldsm_x4(kl[nj][0], kl[nj][1], kl[nj][2], kl[nj][3], sb + ATILE + woff);
            }
#pragma unroll
            for (int nf = 0; nf < 8; nf++) {
                const uint32_t* bh = &kh[nf >> 1][(nf & 1) * 2];
                const uint32_t* bl = &kl[nf >> 1][(nf & 1) * 2];
                mma16816(s[nf], qh[ks], bh);
                mma16816(s[nf], qh[ks], bl);
                mma16816(s[nf], ql[ks], bh);
            }
        }

        if (kt == nkt - 1) {
            const int rl0 = wid * 16 + (lane >> 2);
#pragma unroll
            for (int nf = 0; nf < 8; nf++) {
                int cl = nf * 8 + (lane & 3) * 2;
                if (cl     > rl0)     s[nf][0] = -1e30f;
                if (cl + 1 > rl0)     s[nf][1] = -1e30f;
                if (cl     > rl0 + 8) s[nf][2] = -1e30f;
                if (cl + 1 > rl0 + 8) s[nf][3] = -1e30f;
            }
        }

        float corr[2];
#pragma unroll
        for (int r = 0; r < 2; r++) {
            float mx = -1e30f;
#pragma unroll
            for (int nf = 0; nf < 8; nf++)
                mx = fmaxf(mx, fmaxf(s[nf][2*r], s[nf][2*r + 1]));
            mx = fmaxf(mx, __shfl_xor_sync(0xffffffffu, mx, 1));
            mx = fmaxf(mx, __shfl_xor_sync(0xffffffffu, mx, 2));
            float mnew = fmaxf(m_r[r], mx);
            corr[r] = __expf(m_r[r] - mnew);
            float ps = 0.f;
#pragma unroll
            for (int nf = 0; nf < 8; nf++) {
                float p0 = __expf(s[nf][2*r]     - mnew);
                float p1 = __expf(s[nf][2*r + 1] - mnew);
                s[nf][2*r] = p0; s[nf][2*r + 1] = p1;
                ps += p0 + p1;
            }
            ps += __shfl_xor_sync(0xffffffffu, ps, 1);
            ps += __shfl_xor_sync(0xffffffffu, ps, 2);
            l_r[r] = l_r[r] * corr[r] + ps;
            m_r[r] = mnew;
        }
#pragma unroll
        for (int nf = 0; nf < 8; nf++) {
            o[nf][0] *= corr[0]; o[nf][1] *= corr[0];
            o[nf][2] *= corr[1]; o[nf][3] *= corr[1];
        }

        // ---- O += P V ----
#pragma unroll
        for (int ks2 = 0; ks2 < 4; ks2++) {
            uint32_t pa_h[4], pa_l[4];
            pack_split(s[2*ks2][0],     s[2*ks2][1],     pa_h[0], pa_l[0]);
            pack_split(s[2*ks2][2],     s[2*ks2][3],     pa_h[1], pa_l[1]);
            pack_split(s[2*ks2 + 1][0], s[2*ks2 + 1][1], pa_h[2], pa_l[2]);
            pack_split(s[2*ks2 + 1][2], s[2*ks2 + 1][3], pa_h[3], pa_l[3]);

            uint32_t vh[4][4], vl[4][4];
#pragma unroll
            for (int df = 0; df < 4; df++) {
                uint32_t voff = (uint32_t)(ks2 * 16 + vt_row) * ARSTRIDE + df * 32 + vt_cb;
                ldsm_x4_t(vh[df][0], vh[df][1], vh[df][2], vh[df][3], sb + 2*ATILE + voff);
                ldsm_x4_t(vl[df][0], vl[df][1], vl[df][2], vl[df][3], sb + 3*ATILE + voff);
            }
#pragma unroll
            for (int nf = 0; nf < 8; nf++) {
                const uint32_t* bh = &vh[nf >> 1][(nf & 1) * 2];
                const uint32_t* bl = &vl[nf >> 1][(nf & 1) * 2];
                mma16816(o[nf], pa_h, bh);
                mma16816(o[nf], pa_l, bh);
                mma16816(o[nf], pa_h, bl);
            }
        }
        __syncthreads();
        if (kt + 2 < nkt) { LOAD_KV(kt & 1, kt + 2); CP_COMMIT(); }
    }

    // ---- normalize + split-store Y ----
    const float inv0 = 1.f / l_r[0];
    const float inv1 = 1.f / l_r[1];
    const int grow = qb + wid * 16 + (lane >> 2);
    const int d0 = (lane & 3) * 2;
#pragma unroll
    for (int nf = 0; nf < 8; nf++) {
        uint32_t h0, l0, h1, l1;
        pack_split(o[nf][0] * inv0, o[nf][1] * inv0, h0, l0);
        pack_split(o[nf][2] * inv1, o[nf][3] * inv1, h1, l1);
        size_t p0 = base + (size_t)grow * NE + nf * 8 + d0;
        size_t p1 = base + (size_t)(grow + 8) * NE + nf * 8 + d0;
        *(uint32_t*)(g_Yh + p0) = h0; *(uint32_t*)(g_Yl + p0) = l0;
        *(uint32_t*)(g_Yh + p1) = h1; *(uint32_t*)(g_Yl + p1) = l1;
    }
#undef LOAD_KV
}

// ---------------------------------------------------------------------------
extern "C" void kernel_launch(void* const* d_in, const int* in_sizes, int n_in,
                              void* d_out, int out_size)
{
    const float* x  = (const float*)d_in[0];
    const float* Wq = (const float*)d_in[1];
    const float* bq = (const float*)d_in[2];
    const float* Wk = (const float*)d_in[3];
    const float* bk = (const float*)d_in[4];
    const float* Wv = (const float*)d_in[5];
    const float* bv = (const float*)d_in[6];
    const float* Wo = (const float*)d_in[7];
    const float* bo = (const float*)d_in[8];
    float* out = (float*)d_out;

    __nv_bfloat16 *Xh, *Xl, *WhB, *WlB, *Qh, *Ql, *Kh, *Kl, *Vh, *Vl, *Yh, *Yl;
    cudaGetSymbolAddress((void**)&Xh, g_Xh);  cudaGetSymbolAddress((void**)&Xl, g_Xl);
    cudaGetSymbolAddress((void**)&WhB, g_Wh); cudaGetSymbolAddress((void**)&WlB, g_Wl);
    cudaGetSymbolAddress((void**)&Qh, g_Qh);  cudaGetSymbolAddress((void**)&Ql, g_Ql);
    cudaGetSymbolAddress((void**)&Kh, g_Kh);  cudaGetSymbolAddress((void**)&Kl, g_Kl);
    cudaGetSymbolAddress((void**)&Vh, g_Vh);  cudaGetSymbolAddress((void**)&Vl, g_Vl);
    cudaGetSymbolAddress((void**)&Yh, g_Yh);  cudaGetSymbolAddress((void**)&Yl, g_Yl);

    static bool attr_done = false;
    if (!attr_done) {
        cudaFuncSetAttribute(gemm_s<0>, cudaFuncAttributeMaxDynamicSharedMemorySize, GSMEM);
        cudaFuncSetAttribute(gemm_s<1>, cudaFuncAttributeMaxDynamicSharedMemorySize, GSMEM);
        cudaFuncSetAttribute(attn_tc,   cudaFuncAttributeMaxDynamicSharedMemorySize, ASMEM2);
        attr_done = true;
    }

    // pre-split x and the four weight matrices
    split_one<<<MTOT*NE/1024, 256>>>(x,  Xh, Xl);
    split_one<<<NE*NE/1024,  256>>>(Wq, WhB,              WlB);
    split_one<<<NE*NE/1024,  256>>>(Wk, WhB + 1*NE*NE,    WlB + 1*NE*NE);
    split_one<<<NE*NE/1024,  256>>>(Wv, WhB + 2*NE*NE,    WlB + 2*NE*NE);
    split_one<<<NE*NE/1024,  256>>>(Wo, WhB + 3*NE*NE,    WlB + 3*NE*NE);

    // QKV projections (split outputs, Q pre-scaled)
    gemm_s<0><<<dim3(8, 32, 3), 256, GSMEM>>>(Xh, Xl, WhB, WlB, bq, bk, bv,
                                              Qh, Ql, Kh, Kl, Vh, Vl, nullptr);
    // attention (reads/writes the split globals directly)
    attn_tc<<<dim3(32, 32), 128, ASMEM2>>>();
    // output projection (fp32 out)
    gemm_s<1><<<dim3(8, 32, 1), 256, GSMEM>>>(Yh, Yl, WhB + 3*NE*NE, WlB + 3*NE*NE,
                                              bo, bo, bo,
                                              nullptr, nullptr, nullptr, nullptr, nullptr, nullptr,
                                              out);
}

// round 8
// speedup vs baseline: 1.1233x; 1.1233x over previous
#include <cuda_runtime.h>
#include <cuda_bf16.h>
#include <cstdint>
#include <math.h>

#define TSEQ 2048
#define NE   1024
#define NH   16
#define DKH  64
#define NB   2
#define MTOT (NB*TSEQ)   // 4096

// Pre-split scratch (allocation-free): hi/lo bf16 pairs.
__device__ __nv_bfloat16 g_Xh[MTOT*NE], g_Xl[MTOT*NE];
__device__ __nv_bfloat16 g_Wh[4*NE*NE], g_Wl[4*NE*NE];      // q,k,v,o
__device__ __nv_bfloat16 g_Qh[MTOT*NE], g_Ql[MTOT*NE];
__device__ __nv_bfloat16 g_Kh[MTOT*NE], g_Kl[MTOT*NE];
__device__ __nv_bfloat16 g_Vh[MTOT*NE], g_Vl[MTOT*NE];
__device__ __nv_bfloat16 g_Yh[MTOT*NE], g_Yl[MTOT*NE];

// ---------------------------------------------------------------------------
// Baseline-PTX tensor ops + cp.async (plain sm_103 target)
// ---------------------------------------------------------------------------
static __device__ __forceinline__ uint32_t smem_u32(const void* p) {
    uint32_t a;
    asm("{ .reg .u64 t; cvta.to.shared.u64 t, %1; cvt.u32.u64 %0, t; }" : "=r"(a) : "l"(p));
    return a;
}
static __device__ __forceinline__ void ldsm_x4(uint32_t& r0, uint32_t& r1,
                                               uint32_t& r2, uint32_t& r3, uint32_t a) {
    asm volatile("ldmatrix.sync.aligned.m8n8.x4.shared.b16 {%0,%1,%2,%3}, [%4];"
                 : "=r"(r0), "=r"(r1), "=r"(r2), "=r"(r3) : "r"(a));
}
static __device__ __forceinline__ void ldsm_x4_t(uint32_t& r0, uint32_t& r1,
                                                 uint32_t& r2, uint32_t& r3, uint32_t a) {
    asm volatile("ldmatrix.sync.aligned.m8n8.x4.trans.shared.b16 {%0,%1,%2,%3}, [%4];"
                 : "=r"(r0), "=r"(r1), "=r"(r2), "=r"(r3) : "r"(a));
}
static __device__ __forceinline__ void mma16816(float* c, const uint32_t* a, const uint32_t* b) {
    asm volatile("mma.sync.aligned.m16n8k16.row.col.f32.bf16.bf16.f32 "
                 "{%0,%1,%2,%3}, {%4,%5,%6,%7}, {%8,%9}, {%0,%1,%2,%3};"
                 : "+f"(c[0]), "+f"(c[1]), "+f"(c[2]), "+f"(c[3])
                 : "r"(a[0]), "r"(a[1]), "r"(a[2]), "r"(a[3]), "r"(b[0]), "r"(b[1]));
}
#define CP_A16(dst, src) asm volatile("cp.async.cg.shared.global [%0], [%1], 16;" :: "r"(dst), "l"(src))
#define CP_COMMIT()      asm volatile("cp.async.commit_group;" ::: "memory")
#define CP_WAIT0()       asm volatile("cp.async.wait_group 0;" ::: "memory")
#define CP_WAIT1()       asm volatile("cp.async.wait_group 1;" ::: "memory")

// Split fp32 quad -> hi/lo bf16 quads, store 8B each.
static __device__ __forceinline__ void split_store(char* hi, char* lo, float4 v) {
    __nv_bfloat16 hx = __float2bfloat16_rn(v.x), hy = __float2bfloat16_rn(v.y);
    __nv_bfloat16 hz = __float2bfloat16_rn(v.z), hw = __float2bfloat16_rn(v.w);
    union { __nv_bfloat162 h[2]; uint2 u; } p;
    p.h[0].x = hx; p.h[0].y = hy; p.h[1].x = hz; p.h[1].y = hw;
    *(uint2*)hi = p.u;
    p.h[0].x = __float2bfloat16_rn(v.x - __bfloat162float(hx));
    p.h[0].y = __float2bfloat16_rn(v.y - __bfloat162float(hy));
    p.h[1].x = __float2bfloat16_rn(v.z - __bfloat162float(hz));
    p.h[1].y = __float2bfloat16_rn(v.w - __bfloat162float(hw));
    *(uint2*)lo = p.u;
}
static __device__ __forceinline__ void pack_split(float x, float y, uint32_t& h, uint32_t& l) {
    union { __nv_bfloat162 b; uint32_t u; } ph, pl;
    __nv_bfloat16 hx = __float2bfloat16_rn(x), hy = __float2bfloat16_rn(y);
    ph.b.x = hx; ph.b.y = hy;
    pl.b.x = __float2bfloat16_rn(x - __bfloat162float(hx));
    pl.b.y = __float2bfloat16_rn(y - __bfloat162float(hy));
    h = ph.u; l = pl.u;
}

// ---------------------------------------------------------------------------
// Fused pre-pass: split x and all four weights in one launch.
// Blocks [0,4096): x (4M elems). Blocks [4096,8192): weights (4 x 1M elems).
// ---------------------------------------------------------------------------
__global__ void split_all(const float* __restrict__ x,
                          const float* __restrict__ Wq, const float* __restrict__ Wk,
                          const float* __restrict__ Wv, const float* __restrict__ Wo,
                          __nv_bfloat16* __restrict__ Xh, __nv_bfloat16* __restrict__ Xl,
                          __nv_bfloat16* __restrict__ WhB, __nv_bfloat16* __restrict__ WlB)
{
    const int bx = blockIdx.x;
    if (bx < 4096) {
        size_t i = (size_t)bx * 1024 + threadIdx.x * 4;
        split_store((char*)(Xh + i), (char*)(Xl + i), *(const float4*)(x + i));
    } else {
        const int r = bx - 4096;
        const int w = r >> 10;
        const float* ws = (w == 0) ? Wq : (w == 1) ? Wk : (w == 2) ? Wv : Wo;
        size_t j = (size_t)(r & 1023) * 1024 + threadIdx.x * 4;
        size_t o = (size_t)w * NE * NE + j;
        split_store((char*)(WhB + o), (char*)(WlB + o), *(const float4*)(ws + j));
    }
}

// ---------------------------------------------------------------------------
// GEMM on pre-split operands: C = A * W^T (+bias)(*scale).
// 128x64 CTA tile, 128 threads (4 warps, warp 64x32), kc=32, 2-stage
// cp.async ring, 3 CTAs/SM. MODE 0: split-bf16 out (QKV); MODE 1: fp32 out.
// ---------------------------------------------------------------------------
#define GSTRIDE 80
#define G_AT    (128 * GSTRIDE)          // 10240 (A tile)
#define G_WT    (64 * GSTRIDE)           // 5120  (W tile)
#define G_STAGE (2*G_AT + 2*G_WT)        // 30720 : Ah|Al|Wh|Wl
#define GSMEM   (2 * G_STAGE)            // 61440
#define NKC     (NE / 32)                // 32

template<int MODE>
__global__ void __launch_bounds__(128, 3)
gemm_s(const __nv_bfloat16* __restrict__ Ah, const __nv_bfloat16* __restrict__ Al,
       const __nv_bfloat16* __restrict__ WhB, const __nv_bfloat16* __restrict__ WlB,
       const float* __restrict__ b0, const float* __restrict__ b1, const float* __restrict__ b2,
       __nv_bfloat16* __restrict__ O0h, __nv_bfloat16* __restrict__ O0l,
       __nv_bfloat16* __restrict__ O1h, __nv_bfloat16* __restrict__ O1l,
       __nv_bfloat16* __restrict__ O2h, __nv_bfloat16* __restrict__ O2l,
       float* __restrict__ Fout)
{
    extern __shared__ char smem[];
    const int tid  = threadIdx.x;
    const int wid  = tid >> 5;
    const int lane = tid & 31;
    const int z    = blockIdx.z;
    const __nv_bfloat16* Wh = WhB + (size_t)z * NE * NE;
    const __nv_bfloat16* Wl = WlB + (size_t)z * NE * NE;
    const float* bias = (z == 0) ? b0 : (z == 1) ? b1 : b2;
    const int mbase = blockIdx.y * 128;
    const int nbase = blockIdx.x * 64;
    const uint32_t smb = smem_u32(smem);

    const int warp_m = wid >> 1;        // 0..1
    const int warp_n = wid & 1;         // 0..1
    const int la_row = warp_m * 64 + (lane & 15);
    const int la_k8  = ((lane >> 4) & 1) * 8;
    const int lw_row = warp_n * 32 + (lane & 7) + ((lane >> 4) & 1) * 8;
    const int lw_k8  = ((lane >> 3) & 1) * 8;

    const int lr = tid >> 2;       // 0..31
    const int lc = tid & 3;        // 0..3

    float acc[4][4][4];
#pragma unroll
    for (int mi = 0; mi < 4; mi++)
#pragma unroll
        for (int nf = 0; nf < 4; nf++)
#pragma unroll
            for (int q = 0; q < 4; q++) acc[mi][nf][q] = 0.f;

#define LOAD_STAGE(buf, kt) do {                                              \
        uint32_t sb_ = smb + (buf) * G_STAGE;                                 \
        int kcol_ = (kt) * 32 + lc * 8;                                       \
        _Pragma("unroll")                                                     \
        for (int i = 0; i < 4; i++) {                                         \
            int r_ = lr + 32 * i;                                             \
            CP_A16(sb_ + r_ * GSTRIDE + lc * 16,                              \
                   (const char*)(Ah + (size_t)(mbase + r_) * NE + kcol_));    \
            CP_A16(sb_ + G_AT + r_ * GSTRIDE + lc * 16,                       \
                   (const char*)(Al + (size_t)(mbase + r_) * NE + kcol_));    \
        }                                                                     \
        _Pragma("unroll")                                                     \
        for (int i = 0; i < 2; i++) {                                         \
            int r_ = lr + 32 * i;                                             \
            CP_A16(sb_ + 2*G_AT + r_ * GSTRIDE + lc * 16,                     \
                   (const char*)(Wh + (size_t)(nbase + r_) * NE + kcol_));    \
            CP_A16(sb_ + 2*G_AT + G_WT + r_ * GSTRIDE + lc * 16,              \
                   (const char*)(Wl + (size_t)(nbase + r_) * NE + kcol_));    \
        }                                                                     \
    } while (0)

    LOAD_STAGE(0, 0); CP_COMMIT();
    LOAD_STAGE(1, 1); CP_COMMIT();

    for (int kt = 0; kt < NKC; kt++) {
        if (kt + 1 < NKC) CP_WAIT1(); else CP_WAIT0();
        __syncthreads();

        const uint32_t base = smb + (kt & 1) * G_STAGE;
#pragma unroll
        for (int ks = 0; ks < 2; ks++) {
            uint32_t ah[4][4], al[4][4];
#pragma unroll
            for (int mi = 0; mi < 4; mi++) {
                uint32_t aoff = (uint32_t)(la_row + mi*16) * GSTRIDE + (ks*16 + la_k8) * 2;
                ldsm_x4(ah[mi][0], ah[mi][1], ah[mi][2], ah[mi][3], base + aoff);
                ldsm_x4(al[mi][0], al[mi][1], al[mi][2], al[mi][3], base + G_AT + aoff);
            }
            uint32_t wh[2][4], wl[2][4];
#pragma unroll
            for (int nj = 0; nj < 2; nj++) {
                uint32_t woff = (uint32_t)(lw_row + nj*16) * GSTRIDE + (ks*16 + lw_k8) * 2;
                ldsm_x4(wh[nj][0], wh[nj][1], wh[nj][2], wh[nj][3], base + 2*G_AT + woff);
                ldsm_x4(wl[nj][0], wl[nj][1], wl[nj][2], wl[nj][3], base + 2*G_AT + G_WT + woff);
            }
#pragma unroll
            for (int mi = 0; mi < 4; mi++)
#pragma unroll
                for (int nf = 0; nf < 4; nf++) {
                    const uint32_t* bh = &wh[nf >> 1][(nf & 1) * 2];
                    const uint32_t* bl = &wl[nf >> 1][(nf & 1) * 2];
                    mma16816(acc[mi][nf], ah[mi], bh);
                    mma16816(acc[mi][nf], ah[mi], bl);
                    mma16816(acc[mi][nf], al[mi], bh);
                }
        }
        __syncthreads();
        if (kt + 2 < NKC) { LOAD_STAGE(kt & 1, kt + 2); CP_COMMIT(); }
    }

    // epilogue
    const int crow  = mbase + warp_m * 64 + (lane >> 2);
    const int ccol0 = nbase + warp_n * 32 + (lane & 3) * 2;
    if constexpr (MODE == 0) {
        __nv_bfloat16* Oh = (z == 0) ? O0h : (z == 1) ? O1h : O2h;
        __nv_bfloat16* Ol = (z == 0) ? O0l : (z == 1) ? O1l : O2l;
        const float scale = (z == 0) ? 0.125f : 1.0f;
#pragma unroll
        for (int nf = 0; nf < 4; nf++) {
            float2 bv = *(const float2*)(bias + ccol0 + nf * 8);
#pragma unroll
            for (int mi = 0; mi < 4; mi++) {
                float* c = acc[mi][nf];
                uint32_t h0, l0, h1, l1;
                pack_split((c[0] + bv.x) * scale, (c[1] + bv.y) * scale, h0, l0);
                pack_split((c[2] + bv.x) * scale, (c[3] + bv.y) * scale, h1, l1);
                size_t o0 = (size_t)(crow + mi*16)     * NE + ccol0 + nf*8;
                size_t o1 = (size_t)(crow + mi*16 + 8) * NE + ccol0 + nf*8;
                *(uint32_t*)(Oh + o0) = h0; *(uint32_t*)(Ol + o0) = l0;
                *(uint32_t*)(Oh + o1) = h1; *(uint32_t*)(Ol + o1) = l1;
            }
        }
    } else {
#pragma unroll
        for (int nf = 0; nf < 4; nf++) {
            float2 bv = *(const float2*)(bias + ccol0 + nf * 8);
#pragma unroll
            for (int mi = 0; mi < 4; mi++) {
                float* c = acc[mi][nf];
                *(float2*)(Fout + (size_t)(crow + mi*16)     * NE + ccol0 + nf*8) =
                    make_float2(c[0] + bv.x, c[1] + bv.y);
                *(float2*)(Fout + (size_t)(crow + mi*16 + 8) * NE + ccol0 + nf*8) =
                    make_float2(c[2] + bv.x, c[3] + bv.y);
            }
        }
    }
#undef LOAD_STAGE
}

// ---------------------------------------------------------------------------
// Tensorized flash attention on pre-split Q/K/V; 2-stage cp.async K/V ring.
// CTA: 64 q-rows, 4 warps. Row stride 144B (64 bf16 + pad), conflict-free.
// ---------------------------------------------------------------------------
#define ARSTRIDE 144
#define ATILE    (64 * ARSTRIDE)       // 9216
#define ASTAGE   (4 * ATILE)           // 36864 : Kh|Kl|Vh|Vl
#define ASMEM2   (2 * ASTAGE)          // 73728

__global__ void __launch_bounds__(128, 3)
attn_tc()
{
    extern __shared__ char smem[];
    const int tid  = threadIdx.x;
    const int wid  = tid >> 5;
    const int lane = tid & 31;
    const int qt   = (int)gridDim.x - 1 - (int)blockIdx.x;   // heavy first
    const int bh   = blockIdx.y;
    const int b    = bh >> 4;
    const int h    = bh & 15;
    const size_t base = (size_t)b * TSEQ * NE + (size_t)h * DKH;
    const int qb   = qt * 64;
    const uint32_t smb = smem_u32(smem);

    // ---- stage Q (hi/lo) through buf0, grab fragments ----
#pragma unroll
    for (int i = 0; i < 4; i++) {
        int idx = i * 128 + tid;
        int r = idx >> 3, c = idx & 7;
        uint4 vh = *(const uint4*)(g_Qh + base + (size_t)(qb + r) * NE + c * 8);
        uint4 vl = *(const uint4*)(g_Ql + base + (size_t)(qb + r) * NE + c * 8);
        *(uint4*)(smem + r * ARSTRIDE + c * 16)         = vh;
        *(uint4*)(smem + ATILE + r * ARSTRIDE + c * 16) = vl;
    }
    __syncthreads();

    const int la_row = wid * 16 + (lane & 15);
    const int la_k8  = ((lane >> 4) & 1) * 8;
    uint32_t qh[4][4], ql[4][4];
#pragma unroll
    for (int ks = 0; ks < 4; ks++) {
        uint32_t aoff = (uint32_t)la_row * ARSTRIDE + (ks * 16 + la_k8) * 2;
        ldsm_x4(qh[ks][0], qh[ks][1], qh[ks][2], qh[ks][3], smb + aoff);
        ldsm_x4(ql[ks][0], ql[ks][1], ql[ks][2], ql[ks][3], smb + ATILE + aoff);
    }
    __syncthreads();   // buf0 about to be overwritten by K/V prefetch

    const int lw_row = (lane & 7) + ((lane >> 4) & 1) * 8;
    const int lw_k8  = ((lane >> 3) & 1) * 8;
    const int vt_row = (lane & 7) + ((lane >> 3) & 1) * 8;
    const int vt_cb  = ((lane >> 4) & 1) * 16;

    float m_r[2] = {-1e30f, -1e30f}, l_r[2] = {0.f, 0.f};
    float o[8][4];
#pragma unroll
    for (int nf = 0; nf < 8; nf++)
#pragma unroll
        for (int q = 0; q < 4; q++) o[nf][q] = 0.f;

    const __nv_bfloat16* kvp[4] = { g_Kh, g_Kl, g_Vh, g_Vl };

#define LOAD_KV(buf, kt) do {                                                 \
        uint32_t sb_ = smb + (buf) * ASTAGE;                                  \
        int ktb_ = (kt) * 64;                                                 \
        _Pragma("unroll")                                                     \
        for (int i = 0; i < 16; i++) {                                        \
            int id_ = i * 128 + tid;                                          \
            int t4_ = id_ >> 9;                                               \
            int ix_ = id_ & 511;                                              \
            int r_ = ix_ >> 3, c_ = ix_ & 7;                                  \
            const char* src_ = (const char*)(kvp[t4_] + base +                \
                (size_t)(ktb_ + r_) * NE + c_ * 8);                           \
            CP_A16(sb_ + t4_ * ATILE + r_ * ARSTRIDE + c_ * 16, src_);        \
        }                                                                     \
    } while (0)

    const int nkt = qt + 1;
    LOAD_KV(0, 0); CP_COMMIT();
    if (nkt > 1) { LOAD_KV(1, 1); CP_COMMIT(); }

    for (int kt = 0; kt < nkt; kt++) {
        if (kt + 1 < nkt) CP_WAIT1(); else CP_WAIT0();
        __syncthreads();
        const uint32_t sb = smb + (kt & 1) * ASTAGE;

        // ---- S = Q K^T ----
        float s[8][4];
#pragma unroll
        for (int nf = 0; nf < 8; nf++)
#pragma unroll
            for (int q = 0; q < 4; q++) s[nf][q] = 0.f;

#pragma unroll
        for (int ks = 0; ks < 4; ks++) {
            uint32_t kh[4][4], kl[4][4];
#pragma unroll
            for (int nj = 0; nj < 4; nj++) {
                uint32_t woff = (uint32_t)(nj * 16 + lw_row) * ARSTRIDE + (ks * 16 + lw_k8) * 2;
                ldsm_x4(kh[nj][0], kh[nj][1], kh[nj][2], kh[nj][3], sb + woff);
                ldsm_x4(kl[nj][0], kl[nj][1], kl[nj][2], kl[nj][3], sb + ATILE + woff);
            }
#pragma unroll
            for (int nf = 0; nf < 8; nf++) {
                const uint32_t* bh = &kh[nf >> 1][(nf & 1) * 2];
                const uint32_t* bl = &kl[nf >> 1][(nf & 1) * 2];
                mma16816(s[nf], qh[ks], bh);
                mma16816(s[nf], qh[ks], bl);
                mma16816(s[nf], ql[ks], bh);
            }
        }

        if (kt == nkt - 1) {
            const int rl0 = wid * 16 + (lane >> 2);
#pragma unroll
            for (int nf = 0; nf < 8; nf++) {
                int cl = nf * 8 + (lane & 3) * 2;
                if (cl     > rl0)     s[nf][0] = -1e30f;
                if (cl + 1 > rl0)     s[nf][1] = -1e30f;
                if (cl     > rl0 + 8) s[nf][2] = -1e30f;
                if (cl + 1 > rl0 + 8) s[nf][3] = -1e30f;
            }
        }

        float corr[2];
#pragma unroll
        for (int r = 0; r < 2; r++) {
            float mx = -1e30f;
#pragma unroll
            for (int nf = 0; nf < 8; nf++)
                mx = fmaxf(mx, fmaxf(s[nf][2*r], s[nf][2*r + 1]));
            mx = fmaxf(mx, __shfl_xor_sync(0xffffffffu, mx, 1));
            mx = fmaxf(mx, __shfl_xor_sync(0xffffffffu, mx, 2));
            float mnew = fmaxf(m_r[r], mx);
            corr[r] = __expf(m_r[r] - mnew);
            float ps = 0.f;
#pragma unroll
            for (int nf = 0; nf < 8; nf++) {
                float p0 = __expf(s[nf][2*r]     - mnew);
                float p1 = __expf(s[nf][2*r + 1] - mnew);
                s[nf][2*r] = p0; s[nf][2*r + 1] = p1;
                ps += p0 + p1;
            }
            ps += __shfl_xor_sync(0xffffffffu, ps, 1);
            ps += __shfl_xor_sync(0xffffffffu, ps, 2);
            l_r[r] = l_r[r] * corr[r] + ps;
            m_r[r] = mnew;
        }
#pragma unroll
        for (int nf = 0; nf < 8; nf++) {
            o[nf][0] *= corr[0]; o[nf][1] *= corr[0];
            o[nf][2] *= corr[1]; o[nf][3] *= corr[1];
        }

        // ---- O += P V ----
#pragma unroll
        for (int ks2 = 0; ks2 < 4; ks2++) {
            uint32_t pa_h[4], pa_l[4];
            pack_split(s[2*ks2][0],     s[2*ks2][1],     pa_h[0], pa_l[0]);
            pack_split(s[2*ks2][2],     s[2*ks2][3],     pa_h[1], pa_l[1]);
            pack_split(s[2*ks2 + 1][0], s[2*ks2 + 1][1], pa_h[2], pa_l[2]);
            pack_split(s[2*ks2 + 1][2], s[2*ks2 + 1][3], pa_h[3], pa_l[3]);

            uint32_t vh[4][4], vl[4][4];
#pragma unroll
            for (int df = 0; df < 4; df++) {
                uint32_t voff = (uint32_t)(ks2 * 16 + vt_row) * ARSTRIDE + df * 32 + vt_cb;
                ldsm_x4_t(vh[df][0], vh[df][1], vh[df][2], vh[df][3], sb + 2*ATILE + voff);
                ldsm_x4_t(vl[df][0], vl[df][1], vl[df][2], vl[df][3], sb + 3*ATILE + voff);
            }
#pragma unroll
            for (int nf = 0; nf < 8; nf++) {
                const uint32_t* bh = &vh[nf >> 1][(nf & 1) * 2];
                const uint32_t* bl = &vl[nf >> 1][(nf & 1) * 2];
                mma16816(o[nf], pa_h, bh);
                mma16816(o[nf], pa_l, bh);
                mma16816(o[nf], pa_h, bl);
            }
        }
        __syncthreads();
        if (kt + 2 < nkt) { LOAD_KV(kt & 1, kt + 2); CP_COMMIT(); }
    }

    // ---- normalize + split-store Y ----
    const float inv0 = 1.f / l_r[0];
    const float inv1 = 1.f / l_r[1];
    const int grow = qb + wid * 16 + (lane >> 2);
    const int d0 = (lane & 3) * 2;
#pragma unroll
    for (int nf = 0; nf < 8; nf++) {
        uint32_t h0, l0, h1, l1;
        pack_split(o[nf][0] * inv0, o[nf][1] * inv0, h0, l0);
        pack_split(o[nf][2] * inv1, o[nf][3] * inv1, h1, l1);
        size_t p0 = base + (size_t)grow * NE + nf * 8 + d0;
        size_t p1 = base + (size_t)(grow + 8) * NE + nf * 8 + d0;
        *(uint32_t*)(g_Yh + p0) = h0; *(uint32_t*)(g_Yl + p0) = l0;
        *(uint32_t*)(g_Yh + p1) = h1; *(uint32_t*)(g_Yl + p1) = l1;
    }
#undef LOAD_KV
}

// ---------------------------------------------------------------------------
extern "C" void kernel_launch(void* const* d_in, const int* in_sizes, int n_in,
                              void* d_out, int out_size)
{
    const float* x  = (const float*)d_in[0];
    const float* Wq = (const float*)d_in[1];
    const float* bq = (const float*)d_in[2];
    const float* Wk = (const float*)d_in[3];
    const float* bk = (const float*)d_in[4];
    const float* Wv = (const float*)d_in[5];
    const float* bv = (const float*)d_in[6];
    const float* Wo = (const float*)d_in[7];
    const float* bo = (const float*)d_in[8];
    float* out = (float*)d_out;

    __nv_bfloat16 *Xh, *Xl, *WhB, *WlB, *Qh, *Ql, *Kh, *Kl, *Vh, *Vl, *Yh, *Yl;
    cudaGetSymbolAddress((void**)&Xh, g_Xh);  cudaGetSymbolAddress((void**)&Xl, g_Xl);
    cudaGetSymbolAddress((void**)&WhB, g_Wh); cudaGetSymbolAddress((void**)&WlB, g_Wl);
    cudaGetSymbolAddress((void**)&Qh, g_Qh);  cudaGetSymbolAddress((void**)&Ql, g_Ql);
    cudaGetSymbolAddress((void**)&Kh, g_Kh);  cudaGetSymbolAddress((void**)&Kl, g_Kl);
    cudaGetSymbolAddress((void**)&Vh, g_Vh);  cudaGetSymbolAddress((void**)&Vl, g_Vl);
    cudaGetSymbolAddress((void**)&Yh, g_Yh);  cudaGetSymbolAddress((void**)&Yl, g_Yl);

    static bool attr_done = false;
    if (!attr_done) {
        cudaFuncSetAttribute(gemm_s<0>, cudaFuncAttributeMaxDynamicSharedMemorySize, GSMEM);
        cudaFuncSetAttribute(gemm_s<1>, cudaFuncAttributeMaxDynamicSharedMemorySize, GSMEM);
        cudaFuncSetAttribute(attn_tc,   cudaFuncAttributeMaxDynamicSharedMemorySize, ASMEM2);
        attr_done = true;
    }

    // fused pre-split of x and all four weights
    split_all<<<8192, 256>>>(x, Wq, Wk, Wv, Wo, Xh, Xl, WhB, WlB);

    // QKV projections (split outputs, Q pre-scaled)
    gemm_s<0><<<dim3(16, 32, 3), 128, GSMEM>>>(Xh, Xl, WhB, WlB, bq, bk, bv,
                                               Qh, Ql, Kh, Kl, Vh, Vl, nullptr);
    // attention
    attn_tc<<<dim3(32, 32), 128, ASMEM2>>>();
    // output projection (fp32 out)
    gemm_s<1><<<dim3(16, 32, 1), 128, GSMEM>>>(Yh, Yl, WhB + 3*NE*NE, WlB + 3*NE*NE,
                                               bo, bo, bo,
                                               nullptr, nullptr, nullptr, nullptr, nullptr, nullptr,
                                               out);
}

// round 9
// speedup vs baseline: 1.6863x; 1.5012x over previous
#include <cuda_runtime.h>
#include <cuda_fp16.h>
#include <cstdint>
#include <math.h>

#define TSEQ 2048
#define NE   1024
#define NH   16
#define DKH  64
#define NB   2
#define MTOT (NB*TSEQ)   // 4096

// Scratch (allocation-free), fp16.
__device__ __half g_Xh[MTOT*NE], g_Xl[MTOT*NE];
__device__ __half g_Wh[4*NE*NE];                 // q,k,v,o (hi only)
__device__ __half g_Qh[MTOT*NE];                 // Q pre-scaled by 0.125
__device__ __half g_Kh[MTOT*NE];
__device__ __half g_Vh[MTOT*NE];
__device__ __half g_Yh[MTOT*NE], g_Yl[MTOT*NE]; // attention out, pre-scaled by 64

// ---------------------------------------------------------------------------
// Baseline-PTX tensor ops + cp.async (plain sm_103 target)
// ---------------------------------------------------------------------------
static __device__ __forceinline__ uint32_t smem_u32(const void* p) {
    uint32_t a;
    asm("{ .reg .u64 t; cvta.to.shared.u64 t, %1; cvt.u32.u64 %0, t; }" : "=r"(a) : "l"(p));
    return a;
}
static __device__ __forceinline__ void ldsm_x4(uint32_t& r0, uint32_t& r1,
                                               uint32_t& r2, uint32_t& r3, uint32_t a) {
    asm volatile("ldmatrix.sync.aligned.m8n8.x4.shared.b16 {%0,%1,%2,%3}, [%4];"
                 : "=r"(r0), "=r"(r1), "=r"(r2), "=r"(r3) : "r"(a));
}
static __device__ __forceinline__ void ldsm_x4_t(uint32_t& r0, uint32_t& r1,
                                                 uint32_t& r2, uint32_t& r3, uint32_t a) {
    asm volatile("ldmatrix.sync.aligned.m8n8.x4.trans.shared.b16 {%0,%1,%2,%3}, [%4];"
                 : "=r"(r0), "=r"(r1), "=r"(r2), "=r"(r3) : "r"(a));
}
static __device__ __forceinline__ void mma16816(float* c, const uint32_t* a, const uint32_t* b) {
    asm volatile("mma.sync.aligned.m16n8k16.row.col.f32.f16.f16.f32 "
                 "{%0,%1,%2,%3}, {%4,%5,%6,%7}, {%8,%9}, {%0,%1,%2,%3};"
                 : "+f"(c[0]), "+f"(c[1]), "+f"(c[2]), "+f"(c[3])
                 : "r"(a[0]), "r"(a[1]), "r"(a[2]), "r"(a[3]), "r"(b[0]), "r"(b[1]));
}
#define CP_A16(dst, src) asm volatile("cp.async.cg.shared.global [%0], [%1], 16;" :: "r"(dst), "l"(src))
#define CP_COMMIT()      asm volatile("cp.async.commit_group;" ::: "memory")
#define CP_WAIT0()       asm volatile("cp.async.wait_group 0;" ::: "memory")
#define CP_WAIT1()       asm volatile("cp.async.wait_group 1;" ::: "memory")

static __device__ __forceinline__ uint32_t pack_h2(float x, float y) {
    union { __half2 b; uint32_t u; } p;
    p.b.x = __float2half_rn(x); p.b.y = __float2half_rn(y);
    return p.u;
}
static __device__ __forceinline__ void split_h2(float x, float y, uint32_t& h, uint32_t& l) {
    __half hx = __float2half_rn(x), hy = __float2half_rn(y);
    union { __half2 b; uint32_t u; } ph, pl;
    ph.b.x = hx; ph.b.y = hy;
    pl.b.x = __float2half_rn(x - __half2float(hx));
    pl.b.y = __float2half_rn(y - __half2float(hy));
    h = ph.u; l = pl.u;
}
static __device__ __forceinline__ void split_store4(char* hi, char* lo, float4 v) {
    uint32_t h0, l0, h1, l1;
    split_h2(v.x, v.y, h0, l0);
    split_h2(v.z, v.w, h1, l1);
    *(uint2*)hi = make_uint2(h0, h1);
    *(uint2*)lo = make_uint2(l0, l1);
}

// ---------------------------------------------------------------------------
// Fused pre-pass: x -> (Xh,Xl); Wq,k,v,o -> Wh (hi only).
// ---------------------------------------------------------------------------
__global__ void split_all(const float* __restrict__ x,
                          const float* __restrict__ Wq, const float* __restrict__ Wk,
                          const float* __restrict__ Wv, const float* __restrict__ Wo,
                          __half* __restrict__ Xh, __half* __restrict__ Xl,
                          __half* __restrict__ WhB)
{
    const int bx = blockIdx.x;
    if (bx < 4096) {
        size_t i = (size_t)bx * 1024 + threadIdx.x * 4;
        split_store4((char*)(Xh + i), (char*)(Xl + i), *(const float4*)(x + i));
    } else {
        const int r = bx - 4096;
        const int w = r >> 10;
        const float* ws = (w == 0) ? Wq : (w == 1) ? Wk : (w == 2) ? Wv : Wo;
        size_t j = (size_t)(r & 1023) * 1024 + threadIdx.x * 4;
        float4 v = *(const float4*)(ws + j);
        *(uint2*)(WhB + (size_t)w * NE * NE + j) =
            make_uint2(pack_h2(v.x, v.y), pack_h2(v.z, v.w));
    }
}

// ---------------------------------------------------------------------------
// GEMM: C = A * Wh^T, A = (Ah + Al) full split, W hi-only. 2 MMA terms.
// 128x64 CTA tile, 128 threads, kc=32, 2-stage cp.async ring, 3 CTAs/SM.
// MODE 0: fp16-hi output (QKV; z=0 scaled 0.125). MODE 1: fp32 out, scale 1/64.
// ---------------------------------------------------------------------------
#define GSTRIDE 80
#define G_AT    (128 * GSTRIDE)          // 10240
#define G_WT    (64 * GSTRIDE)           // 5120
#define G_STAGE (2*G_AT + G_WT)          // 25600 : Ah|Al|Wh
#define GSMEM   (2 * G_STAGE)            // 51200
#define NKC     (NE / 32)                // 32

template<int MODE>
__global__ void __launch_bounds__(128, 3)
gemm_s(const __half* __restrict__ Ah, const __half* __restrict__ Al,
       const __half* __restrict__ WhB,
       const float* __restrict__ b0, const float* __restrict__ b1, const float* __restrict__ b2,
       __half* __restrict__ O0, __half* __restrict__ O1, __half* __restrict__ O2,
       float* __restrict__ Fout)
{
    extern __shared__ char smem[];
    const int tid  = threadIdx.x;
    const int wid  = tid >> 5;
    const int lane = tid & 31;
    const int z    = blockIdx.z;
    const __half* Wh = WhB + (size_t)z * NE * NE;
    const float* bias = (z == 0) ? b0 : (z == 1) ? b1 : b2;
    const int mbase = blockIdx.y * 128;
    const int nbase = blockIdx.x * 64;
    const uint32_t smb = smem_u32(smem);

    const int warp_m = wid >> 1;
    const int warp_n = wid & 1;
    const int la_row = warp_m * 64 + (lane & 15);
    const int la_k8  = ((lane >> 4) & 1) * 8;
    const int lw_row = warp_n * 32 + (lane & 7) + ((lane >> 4) & 1) * 8;
    const int lw_k8  = ((lane >> 3) & 1) * 8;

    const int lr = tid >> 2;       // 0..31
    const int lc = tid & 3;        // 0..3

    float acc[4][4][4];
#pragma unroll
    for (int mi = 0; mi < 4; mi++)
#pragma unroll
        for (int nf = 0; nf < 4; nf++)
#pragma unroll
            for (int q = 0; q < 4; q++) acc[mi][nf][q] = 0.f;

#define LOAD_STAGE(buf, kt) do {                                              \
        uint32_t sb_ = smb + (buf) * G_STAGE;                                 \
        int kcol_ = (kt) * 32 + lc * 8;                                       \
        _Pragma("unroll")                                                     \
        for (int i = 0; i < 4; i++) {                                         \
            int r_ = lr + 32 * i;                                             \
            CP_A16(sb_ + r_ * GSTRIDE + lc * 16,                              \
                   (const char*)(Ah + (size_t)(mbase + r_) * NE + kcol_));    \
            CP_A16(sb_ + G_AT + r_ * GSTRIDE + lc * 16,                       \
                   (const char*)(Al + (size_t)(mbase + r_) * NE + kcol_));    \
        }                                                                     \
        _Pragma("unroll")                                                     \
        for (int i = 0; i < 2; i++) {                                         \
            int r_ = lr + 32 * i;                                             \
            CP_A16(sb_ + 2*G_AT + r_ * GSTRIDE + lc * 16,                     \
                   (const char*)(Wh + (size_t)(nbase + r_) * NE + kcol_));    \
        }                                                                     \
    } while (0)

    LOAD_STAGE(0, 0); CP_COMMIT();
    LOAD_STAGE(1, 1); CP_COMMIT();

    for (int kt = 0; kt < NKC; kt++) {
        if (kt + 1 < NKC) CP_WAIT1(); else CP_WAIT0();
        __syncthreads();

        const uint32_t base = smb + (kt & 1) * G_STAGE;
#pragma unroll
        for (int ks = 0; ks < 2; ks++) {
            uint32_t ah[4][4], al[4][4];
#pragma unroll
            for (int mi = 0; mi < 4; mi++) {
                uint32_t aoff = (uint32_t)(la_row + mi*16) * GSTRIDE + (ks*16 + la_k8) * 2;
                ldsm_x4(ah[mi][0], ah[mi][1], ah[mi][2], ah[mi][3], base + aoff);
                ldsm_x4(al[mi][0], al[mi][1], al[mi][2], al[mi][3], base + G_AT + aoff);
            }
            uint32_t wh[2][4];
#pragma unroll
            for (int nj = 0; nj < 2; nj++) {
                uint32_t woff = (uint32_t)(lw_row + nj*16) * GSTRIDE + (ks*16 + lw_k8) * 2;
                ldsm_x4(wh[nj][0], wh[nj][1], wh[nj][2], wh[nj][3], base + 2*G_AT + woff);
            }
#pragma unroll
            for (int mi = 0; mi < 4; mi++)
#pragma unroll
                for (int nf = 0; nf < 4; nf++) {
                    const uint32_t* bh = &wh[nf >> 1][(nf & 1) * 2];
                    mma16816(acc[mi][nf], ah[mi], bh);
                    mma16816(acc[mi][nf], al[mi], bh);
                }
        }
        __syncthreads();
        if (kt + 2 < NKC) { LOAD_STAGE(kt & 1, kt + 2); CP_COMMIT(); }
    }

    // epilogue
    const int crow  = mbase + warp_m * 64 + (lane >> 2);
    const int ccol0 = nbase + warp_n * 32 + (lane & 3) * 2;
    if constexpr (MODE == 0) {
        __half* O = (z == 0) ? O0 : (z == 1) ? O1 : O2;
        const float scale = (z == 0) ? 0.125f : 1.0f;
#pragma unroll
        for (int nf = 0; nf < 4; nf++) {
            float2 bv = *(const float2*)(bias + ccol0 + nf * 8);
#pragma unroll
            for (int mi = 0; mi < 4; mi++) {
                float* c = acc[mi][nf];
                size_t o0 = (size_t)(crow + mi*16)     * NE + ccol0 + nf*8;
                size_t o1 = (size_t)(crow + mi*16 + 8) * NE + ccol0 + nf*8;
                *(uint32_t*)(O + o0) = pack_h2((c[0] + bv.x) * scale, (c[1] + bv.y) * scale);
                *(uint32_t*)(O + o1) = pack_h2((c[2] + bv.x) * scale, (c[3] + bv.y) * scale);
            }
        }
    } else {
        // A was Y pre-scaled by 64 -> undo with exact 1/64, then bias.
#pragma unroll
        for (int nf = 0; nf < 4; nf++) {
            float2 bv = *(const float2*)(bias + ccol0 + nf * 8);
#pragma unroll
            for (int mi = 0; mi < 4; mi++) {
                float* c = acc[mi][nf];
                *(float2*)(Fout + (size_t)(crow + mi*16)     * NE + ccol0 + nf*8) =
                    make_float2(c[0] * 0.015625f + bv.x, c[1] * 0.015625f + bv.y);
                *(float2*)(Fout + (size_t)(crow + mi*16 + 8) * NE + ccol0 + nf*8) =
                    make_float2(c[2] * 0.015625f + bv.x, c[3] * 0.015625f + bv.y);
            }
        }
    }
#undef LOAD_STAGE
}

// ---------------------------------------------------------------------------
// Flash attention, 1-term fp16 mma (S = Qh*Kh^T, O += Ph*Vh).
// CTA: 64 q-rows, 4 warps. Kh|Vh per stage, 2-stage cp.async ring.
// ---------------------------------------------------------------------------
#define ARSTRIDE 144
#define ATILE    (64 * ARSTRIDE)       // 9216
#define ASTAGE   (2 * ATILE)           // 18432 : Kh|Vh
#define ASMEM2   (2 * ASTAGE)          // 36864

__global__ void __launch_bounds__(128, 3)
attn_tc()
{
    extern __shared__ char smem[];
    const int tid  = threadIdx.x;
    const int wid  = tid >> 5;
    const int lane = tid & 31;
    const int qt   = (int)gridDim.x - 1 - (int)blockIdx.x;   // heavy first
    const int bh   = blockIdx.y;
    const int b    = bh >> 4;
    const int h    = bh & 15;
    const size_t base = (size_t)b * TSEQ * NE + (size_t)h * DKH;
    const int qb   = qt * 64;
    const uint32_t smb = smem_u32(smem);

    // ---- stage Qh through buf0, grab fragments ----
#pragma unroll
    for (int i = 0; i < 4; i++) {
        int idx = i * 128 + tid;
        int r = idx >> 3, c = idx & 7;
        *(uint4*)(smem + r * ARSTRIDE + c * 16) =
            *(const uint4*)(g_Qh + base + (size_t)(qb + r) * NE + c * 8);
    }
    __syncthreads();

    const int la_row = wid * 16 + (lane & 15);
    const int la_k8  = ((lane >> 4) & 1) * 8;
    uint32_t qh[4][4];
#pragma unroll
    for (int ks = 0; ks < 4; ks++) {
        uint32_t aoff = (uint32_t)la_row * ARSTRIDE + (ks * 16 + la_k8) * 2;
        ldsm_x4(qh[ks][0], qh[ks][1], qh[ks][2], qh[ks][3], smb + aoff);
    }
    __syncthreads();   // buf0 about to be overwritten by K/V prefetch

    const int lw_row = (lane & 7) + ((lane >> 4) & 1) * 8;
    const int lw_k8  = ((lane >> 3) & 1) * 8;
    const int vt_row = (lane & 7) + ((lane >> 3) & 1) * 8;
    const int vt_cb  = ((lane >> 4) & 1) * 16;

    float m_r[2] = {-1e30f, -1e30f}, l_r[2] = {0.f, 0.f};
    float o[8][4];
#pragma unroll
    for (int nf = 0; nf < 8; nf++)
#pragma unroll
        for (int q = 0; q < 4; q++) o[nf][q] = 0.f;

    const __half* kvp[2] = { g_Kh, g_Vh };

#define LOAD_KV(buf, kt) do {                                                 \
        uint32_t sb_ = smb + (buf) * ASTAGE;                                  \
        int ktb_ = (kt) * 64;                                                 \
        _Pragma("unroll")                                                     \
        for (int i = 0; i < 8; i++) {                                         \
            int id_ = i * 128 + tid;                                          \
            int t2_ = id_ >> 9;                                               \
            int ix_ = id_ & 511;                                              \
            int r_ = ix_ >> 3, c_ = ix_ & 7;                                  \
            const char* src_ = (const char*)(kvp[t2_] + base +                \
                (size_t)(ktb_ + r_) * NE + c_ * 8);                           \
            CP_A16(sb_ + t2_ * ATILE + r_ * ARSTRIDE + c_ * 16, src_);        \
        }                                                                     \
    } while (0)

    const int nkt = qt + 1;
    LOAD_KV(0, 0); CP_COMMIT();
    if (nkt > 1) { LOAD_KV(1, 1); CP_COMMIT(); }

    for (int kt = 0; kt < nkt; kt++) {
        if (kt + 1 < nkt) CP_WAIT1(); else CP_WAIT0();
        __syncthreads();
        const uint32_t sb = smb + (kt & 1) * ASTAGE;

        // ---- S = Qh Kh^T ----
        float s[8][4];
#pragma unroll
        for (int nf = 0; nf < 8; nf++)
#pragma unroll
            for (int q = 0; q < 4; q++) s[nf][q] = 0.f;

#pragma unroll
        for (int ks = 0; ks < 4; ks++) {
            uint32_t kh[4][4];
#pragma unroll
            for (int nj = 0; nj < 4; nj++) {
                uint32_t woff = (uint32_t)(nj * 16 + lw_row) * ARSTRIDE + (ks * 16 + lw_k8) * 2;
                ldsm_x4(kh[nj][0], kh[nj][1], kh[nj][2], kh[nj][3], sb + woff);
            }
#pragma unroll
            for (int nf = 0; nf < 8; nf++)
                mma16816(s[nf], qh[ks], &kh[nf >> 1][(nf & 1) * 2]);
        }

        if (kt == nkt - 1) {
            const int rl0 = wid * 16 + (lane >> 2);
#pragma unroll
            for (int nf = 0; nf < 8; nf++) {
                int cl = nf * 8 + (lane & 3) * 2;
                if (cl     > rl0)     s[nf][0] = -1e30f;
                if (cl + 1 > rl0)     s[nf][1] = -1e30f;
                if (cl     > rl0 + 8) s[nf][2] = -1e30f;
                if (cl + 1 > rl0 + 8) s[nf][3] = -1e30f;
            }
        }

        float corr[2];
#pragma unroll
        for (int r = 0; r < 2; r++) {
            float mx = -1e30f;
#pragma unroll
            for (int nf = 0; nf < 8; nf++)
                mx = fmaxf(mx, fmaxf(s[nf][2*r], s[nf][2*r + 1]));
            mx = fmaxf(mx, __shfl_xor_sync(0xffffffffu, mx, 1));
            mx = fmaxf(mx, __shfl_xor_sync(0xffffffffu, mx, 2));
            float mnew = fmaxf(m_r[r], mx);
            corr[r] = __expf(m_r[r] - mnew);
            float ps = 0.f;
#pragma unroll
            for (int nf = 0; nf < 8; nf++) {
                float p0 = __expf(s[nf][2*r]     - mnew);
                float p1 = __expf(s[nf][2*r + 1] - mnew);
                s[nf][2*r] = p0; s[nf][2*r + 1] = p1;
                ps += p0 + p1;
            }
            ps += __shfl_xor_sync(0xffffffffu, ps, 1);
            ps += __shfl_xor_sync(0xffffffffu, ps, 2);
            l_r[r] = l_r[r] * corr[r] + ps;
            m_r[r] = mnew;
        }
#pragma unroll
        for (int nf = 0; nf < 8; nf++) {
            o[nf][0] *= corr[0]; o[nf][1] *= corr[0];
            o[nf][2] *= corr[1]; o[nf][3] *= corr[1];
        }

        // ---- O += Ph Vh ----
#pragma unroll
        for (int ks2 = 0; ks2 < 4; ks2++) {
            uint32_t pa_h[4];
            pa_h[0] = pack_h2(s[2*ks2][0],     s[2*ks2][1]);
            pa_h[1] = pack_h2(s[2*ks2][2],     s[2*ks2][3]);
            pa_h[2] = pack_h2(s[2*ks2 + 1][0], s[2*ks2 + 1][1]);
            pa_h[3] = pack_h2(s[2*ks2 + 1][2], s[2*ks2 + 1][3]);

            uint32_t vh[4][4];
#pragma unroll
            for (int df = 0; df < 4; df++) {
                uint32_t voff = (uint32_t)(ks2 * 16 + vt_row) * ARSTRIDE + df * 32 + vt_cb;
                ldsm_x4_t(vh[df][0], vh[df][1], vh[df][2], vh[df][3], sb + ATILE + voff);
            }
#pragma unroll
            for (int nf = 0; nf < 8; nf++)
                mma16816(o[nf], pa_h, &vh[nf >> 1][(nf & 1) * 2]);
        }
        __syncthreads();
        if (kt + 2 < nkt) { LOAD_KV(kt & 1, kt + 2); CP_COMMIT(); }
    }

    // ---- normalize, scale by 64, split-store Y ----
    const float inv0 = 64.f / l_r[0];
    const float inv1 = 64.f / l_r[1];
    const int grow = qb + wid * 16 + (lane >> 2);
    const int d0 = (lane & 3) * 2;
#pragma unroll
    for (int nf = 0; nf < 8; nf++) {
        uint32_t h0, l0, h1, l1;
        split_h2(o[nf][0] * inv0, o[nf][1] * inv0, h0, l0);
        split_h2(o[nf][2] * inv1, o[nf][3] * inv1, h1, l1);
        size_t p0 = base + (size_t)grow * NE + nf * 8 + d0;
        size_t p1 = base + (size_t)(grow + 8) * NE + nf * 8 + d0;
        *(uint32_t*)(g_Yh + p0) = h0; *(uint32_t*)(g_Yl + p0) = l0;
        *(uint32_t*)(g_Yh + p1) = h1; *(uint32_t*)(g_Yl + p1) = l1;
    }
#undef LOAD_KV
}

// ---------------------------------------------------------------------------
extern "C" void kernel_launch(void* const* d_in, const int* in_sizes, int n_in,
                              void* d_out, int out_size)
{
    const float* x  = (const float*)d_in[0];
    const float* Wq = (const float*)d_in[1];
    const float* bq = (const float*)d_in[2];
    const float* Wk = (const float*)d_in[3];
    const float* bk = (const float*)d_in[4];
    const float* Wv = (const float*)d_in[5];
    const float* bv = (const float*)d_in[6];
    const float* Wo = (const float*)d_in[7];
    const float* bo = (const float*)d_in[8];
    float* out = (float*)d_out;

    __half *Xh, *Xl, *WhB, *Qh, *Kh, *Vh, *Yh, *Yl;
    cudaGetSymbolAddress((void**)&Xh, g_Xh);  cudaGetSymbolAddress((void**)&Xl, g_Xl);
    cudaGetSymbolAddress((void**)&WhB, g_Wh);
    cudaGetSymbolAddress((void**)&Qh, g_Qh);
    cudaGetSymbolAddress((void**)&Kh, g_Kh);
    cudaGetSymbolAddress((void**)&Vh, g_Vh);
    cudaGetSymbolAddress((void**)&Yh, g_Yh);  cudaGetSymbolAddress((void**)&Yl, g_Yl);

    static bool attr_done = false;
    if (!attr_done) {
        cudaFuncSetAttribute(gemm_s<0>, cudaFuncAttributeMaxDynamicSharedMemorySize, GSMEM);
        cudaFuncSetAttribute(gemm_s<1>, cudaFuncAttributeMaxDynamicSharedMemorySize, GSMEM);
        attr_done = true;
    }

    // fused pre-split of x (hi/lo) and all four weights (hi)
    split_all<<<8192, 256>>>(x, Wq, Wk, Wv, Wo, Xh, Xl, WhB);

    // QKV projections (fp16-hi outputs, Q pre-scaled by 0.125)
    gemm_s<0><<<dim3(16, 32, 3), 128, GSMEM>>>(Xh, Xl, WhB, bq, bk, bv,
                                               Qh, Kh, Vh, nullptr);
    // attention (1-term S and PV, Y = 64*O split fp16)
    attn_tc<<<dim3(32, 32), 128, ASMEM2>>>();
    // output projection (fp32 out, undoes the 64x)
    gemm_s<1><<<dim3(16, 32, 1), 128, GSMEM>>>(Yh, Yl, WhB + 3*(size_t)NE*NE, bo, bo, bo,
                                               nullptr, nullptr, nullptr, out);
}

// round 10
// speedup vs baseline: 2.1370x; 1.2673x over previous
#include <cuda_runtime.h>
#include <cuda_fp16.h>
#include <cstdint>
#include <math.h>

#define TSEQ 2048
#define NE   1024
#define NH   16
#define DKH  64
#define NB   2
#define MTOT (NB*TSEQ)   // 4096

// Scratch (allocation-free), fp16.
__device__ __half g_Xh[MTOT*NE];
__device__ __half g_Wh[4*NE*NE];                 // q,k,v,o (hi only)
__device__ __half g_Qh[MTOT*NE];                 // Q pre-scaled by 0.125
__device__ __half g_Kh[MTOT*NE];
__device__ __half g_Vh[MTOT*NE];
__device__ __half g_Yh[MTOT*NE], g_Yl[MTOT*NE]; // attention out, pre-scaled by 64

// ---------------------------------------------------------------------------
// Baseline-PTX tensor ops + cp.async (plain sm_103 target)
// ---------------------------------------------------------------------------
static __device__ __forceinline__ uint32_t smem_u32(const void* p) {
    uint32_t a;
    asm("{ .reg .u64 t; cvta.to.shared.u64 t, %1; cvt.u32.u64 %0, t; }" : "=r"(a) : "l"(p));
    return a;
}
static __device__ __forceinline__ void ldsm_x4(uint32_t& r0, uint32_t& r1,
                                               uint32_t& r2, uint32_t& r3, uint32_t a) {
    asm volatile("ldmatrix.sync.aligned.m8n8.x4.shared.b16 {%0,%1,%2,%3}, [%4];"
                 : "=r"(r0), "=r"(r1), "=r"(r2), "=r"(r3) : "r"(a));
}
static __device__ __forceinline__ void ldsm_x4_t(uint32_t& r0, uint32_t& r1,
                                                 uint32_t& r2, uint32_t& r3, uint32_t a) {
    asm volatile("ldmatrix.sync.aligned.m8n8.x4.trans.shared.b16 {%0,%1,%2,%3}, [%4];"
                 : "=r"(r0), "=r"(r1), "=r"(r2), "=r"(r3) : "r"(a));
}
static __device__ __forceinline__ void mma16816(float* c, const uint32_t* a, const uint32_t* b) {
    asm volatile("mma.sync.aligned.m16n8k16.row.col.f32.f16.f16.f32 "
                 "{%0,%1,%2,%3}, {%4,%5,%6,%7}, {%8,%9}, {%0,%1,%2,%3};"
                 : "+f"(c[0]), "+f"(c[1]), "+f"(c[2]), "+f"(c[3])
                 : "r"(a[0]), "r"(a[1]), "r"(a[2]), "r"(a[3]), "r"(b[0]), "r"(b[1]));
}
#define CP_A16(dst, src) asm volatile("cp.async.cg.shared.global [%0], [%1], 16;" :: "r"(dst), "l"(src))
#define CP_COMMIT()      asm volatile("cp.async.commit_group;" ::: "memory")
#define CP_WAIT0()       asm volatile("cp.async.wait_group 0;" ::: "memory")
#define CP_WAIT1()       asm volatile("cp.async.wait_group 1;" ::: "memory")

static __device__ __forceinline__ uint32_t pack_h2(float x, float y) {
    union { __half2 b; uint32_t u; } p;
    p.b.x = __float2half_rn(x); p.b.y = __float2half_rn(y);
    return p.u;
}
static __device__ __forceinline__ void split_h2(float x, float y, uint32_t& h, uint32_t& l) {
    __half hx = __float2half_rn(x), hy = __float2half_rn(y);
    union { __half2 b; uint32_t u; } ph, pl;
    ph.b.x = hx; ph.b.y = hy;
    pl.b.x = __float2half_rn(x - __half2float(hx));
    pl.b.y = __float2half_rn(y - __half2float(hy));
    h = ph.u; l = pl.u;
}

// ---------------------------------------------------------------------------
// Fused pre-pass: x -> Xh; Wq,k,v,o -> Wh. (hi-only everywhere)
// ---------------------------------------------------------------------------
__global__ void split_all(const float* __restrict__ x,
                          const float* __restrict__ Wq, const float* __restrict__ Wk,
                          const float* __restrict__ Wv, const float* __restrict__ Wo,
                          __half* __restrict__ Xh, __half* __restrict__ WhB)
{
    const int bx = blockIdx.x;
    if (bx < 4096) {
        size_t i = (size_t)bx * 1024 + threadIdx.x * 4;
        float4 v = *(const float4*)(x + i);
        *(uint2*)(Xh + i) = make_uint2(pack_h2(v.x, v.y), pack_h2(v.z, v.w));
    } else {
        const int r = bx - 4096;
        const int w = r >> 10;
        const float* ws = (w == 0) ? Wq : (w == 1) ? Wk : (w == 2) ? Wv : Wo;
        size_t j = (size_t)(r & 1023) * 1024 + threadIdx.x * 4;
        float4 v = *(const float4*)(ws + j);
        *(uint2*)(WhB + (size_t)w * NE * NE + j) =
            make_uint2(pack_h2(v.x, v.y), pack_h2(v.z, v.w));
    }
}

// ---------------------------------------------------------------------------
// Shared GEMM tiling constants. 128x64 CTA tile, 128 threads, kc=32,
// 2-stage cp.async ring, 3 CTAs/SM.
// ---------------------------------------------------------------------------
#define GSTRIDE 80
#define G_AT    (128 * GSTRIDE)          // 10240
#define G_WT    (64 * GSTRIDE)           // 5120
#define NKC     (NE / 32)                // 32

// ---- QKV GEMM: 1 term (Xh * Wh^T), fp16-hi output (z=0 scaled 0.125) ----
#define Q_STAGE (G_AT + G_WT)            // 15360 : Ah|Wh
#define QSMEM   (2 * Q_STAGE)            // 30720

__global__ void __launch_bounds__(128, 3)
gemm_qkv(const __half* __restrict__ Ah, const __half* __restrict__ WhB,
         const float* __restrict__ b0, const float* __restrict__ b1, const float* __restrict__ b2,
         __half* __restrict__ O0, __half* __restrict__ O1, __half* __restrict__ O2)
{
    extern __shared__ char smem[];
    const int tid  = threadIdx.x;
    const int wid  = tid >> 5;
    const int lane = tid & 31;
    const int z    = blockIdx.z;
    const __half* Wh = WhB + (size_t)z * NE * NE;
    const float* bias = (z == 0) ? b0 : (z == 1) ? b1 : b2;
    const int mbase = blockIdx.y * 128;
    const int nbase = blockIdx.x * 64;
    const uint32_t smb = smem_u32(smem);

    const int warp_m = wid >> 1;
    const int warp_n = wid & 1;
    const int la_row = warp_m * 64 + (lane & 15);
    const int la_k8  = ((lane >> 4) & 1) * 8;
    const int lw_row = warp_n * 32 + (lane & 7) + ((lane >> 4) & 1) * 8;
    const int lw_k8  = ((lane >> 3) & 1) * 8;

    const int lr = tid >> 2;       // 0..31
    const int lc = tid & 3;        // 0..3

    float acc[4][4][4];
#pragma unroll
    for (int mi = 0; mi < 4; mi++)
#pragma unroll
        for (int nf = 0; nf < 4; nf++)
#pragma unroll
            for (int q = 0; q < 4; q++) acc[mi][nf][q] = 0.f;

#define LOAD_Q(buf, kt) do {                                                  \
        uint32_t sb_ = smb + (buf) * Q_STAGE;                                 \
        int kcol_ = (kt) * 32 + lc * 8;                                       \
        _Pragma("unroll")                                                     \
        for (int i = 0; i < 4; i++) {                                         \
            int r_ = lr + 32 * i;                                             \
            CP_A16(sb_ + r_ * GSTRIDE + lc * 16,                              \
                   (const char*)(Ah + (size_t)(mbase + r_) * NE + kcol_));    \
        }                                                                     \
        _Pragma("unroll")                                                     \
        for (int i = 0; i < 2; i++) {                                         \
            int r_ = lr + 32 * i;                                             \
            CP_A16(sb_ + G_AT + r_ * GSTRIDE + lc * 16,                       \
                   (const char*)(Wh + (size_t)(nbase + r_) * NE + kcol_));    \
        }                                                                     \
    } while (0)

    LOAD_Q(0, 0); CP_COMMIT();
    LOAD_Q(1, 1); CP_COMMIT();

    for (int kt = 0; kt < NKC; kt++) {
        if (kt + 1 < NKC) CP_WAIT1(); else CP_WAIT0();
        __syncthreads();

        const uint32_t base = smb + (kt & 1) * Q_STAGE;
#pragma unroll
        for (int ks = 0; ks < 2; ks++) {
            uint32_t ah[4][4];
#pragma unroll
            for (int mi = 0; mi < 4; mi++) {
                uint32_t aoff = (uint32_t)(la_row + mi*16) * GSTRIDE + (ks*16 + la_k8) * 2;
                ldsm_x4(ah[mi][0], ah[mi][1], ah[mi][2], ah[mi][3], base + aoff);
            }
            uint32_t wh[2][4];
#pragma unroll
            for (int nj = 0; nj < 2; nj++) {
                uint32_t woff = (uint32_t)(lw_row + nj*16) * GSTRIDE + (ks*16 + lw_k8) * 2;
                ldsm_x4(wh[nj][0], wh[nj][1], wh[nj][2], wh[nj][3], base + G_AT + woff);
            }
#pragma unroll
            for (int mi = 0; mi < 4; mi++)
#pragma unroll
                for (int nf = 0; nf < 4; nf++)
                    mma16816(acc[mi][nf], ah[mi], &wh[nf >> 1][(nf & 1) * 2]);
        }
        __syncthreads();
        if (kt + 2 < NKC) { LOAD_Q(kt & 1, kt + 2); CP_COMMIT(); }
    }

    const int crow  = mbase + warp_m * 64 + (lane >> 2);
    const int ccol0 = nbase + warp_n * 32 + (lane & 3) * 2;
    __half* O = (z == 0) ? O0 : (z == 1) ? O1 : O2;
    const float scale = (z == 0) ? 0.125f : 1.0f;
#pragma unroll
    for (int nf = 0; nf < 4; nf++) {
        float2 bv = *(const float2*)(bias + ccol0 + nf * 8);
#pragma unroll
        for (int mi = 0; mi < 4; mi++) {
            float* c = acc[mi][nf];
            size_t o0 = (size_t)(crow + mi*16)     * NE + ccol0 + nf*8;
            size_t o1 = (size_t)(crow + mi*16 + 8) * NE + ccol0 + nf*8;
            *(uint32_t*)(O + o0) = pack_h2((c[0] + bv.x) * scale, (c[1] + bv.y) * scale);
            *(uint32_t*)(O + o1) = pack_h2((c[2] + bv.x) * scale, (c[3] + bv.y) * scale);
        }
    }
#undef LOAD_Q
}

// ---- Out-proj GEMM: 2 terms ((Yh+Yl) * Wh^T), fp32 out, undoes the 64x ----
#define P_STAGE (2*G_AT + G_WT)          // 25600 : Ah|Al|Wh
#define PSMEM   (2 * P_STAGE)            // 51200

__global__ void __launch_bounds__(128, 3)
gemm_proj(const __half* __restrict__ Ah, const __half* __restrict__ Al,
          const __half* __restrict__ Wh, const float* __restrict__ bias,
          float* __restrict__ Fout)
{
    extern __shared__ char smem[];
    const int tid  = threadIdx.x;
    const int wid  = tid >> 5;
    const int lane = tid & 31;
    const int mbase = blockIdx.y * 128;
    const int nbase = blockIdx.x * 64;
    const uint32_t smb = smem_u32(smem);

    const int warp_m = wid >> 1;
    const int warp_n = wid & 1;
    const int la_row = warp_m * 64 + (lane & 15);
    const int la_k8  = ((lane >> 4) & 1) * 8;
    const int lw_row = warp_n * 32 + (lane & 7) + ((lane >> 4) & 1) * 8;
    const int lw_k8  = ((lane >> 3) & 1) * 8;

    const int lr = tid >> 2;
    const int lc = tid & 3;

    float acc[4][4][4];
#pragma unroll
    for (int mi = 0; mi < 4; mi++)
#pragma unroll
        for (int nf = 0; nf < 4; nf++)
#pragma unroll
            for (int q = 0; q < 4; q++) acc[mi][nf][q] = 0.f;

#define LOAD_P(buf, kt) do {                                                  \
        uint32_t sb_ = smb + (buf) * P_STAGE;                                 \
        int kcol_ = (kt) * 32 + lc * 8;                                       \
        _Pragma("unroll")                                                     \
        for (int i = 0; i < 4; i++) {                                         \
            int r_ = lr + 32 * i;                                             \
            CP_A16(sb_ + r_ * GSTRIDE + lc * 16,                              \
                   (const char*)(Ah + (size_t)(mbase + r_) * NE + kcol_));    \
            CP_A16(sb_ + G_AT + r_ * GSTRIDE + lc * 16,                       \
                   (const char*)(Al + (size_t)(mbase + r_) * NE + kcol_));    \
        }                                                                     \
        _Pragma("unroll")                                                     \
        for (int i = 0; i < 2; i++) {                                         \
            int r_ = lr + 32 * i;                                             \
            CP_A16(sb_ + 2*G_AT + r_ * GSTRIDE + lc * 16,                     \
                   (const char*)(Wh + (size_t)(nbase + r_) * NE + kcol_));    \
        }                                                                     \
    } while (0)

    LOAD_P(0, 0); CP_COMMIT();
    LOAD_P(1, 1); CP_COMMIT();

    for (int kt = 0; kt < NKC; kt++) {
        if (kt + 1 < NKC) CP_WAIT1(); else CP_WAIT0();
        __syncthreads();

        const uint32_t base = smb + (kt & 1) * P_STAGE;
#pragma unroll
        for (int ks = 0; ks < 2; ks++) {
            uint32_t ah[4][4], al[4][4];
#pragma unroll
            for (int mi = 0; mi < 4; mi++) {
                uint32_t aoff = (uint32_t)(la_row + mi*16) * GSTRIDE + (ks*16 + la_k8) * 2;
                ldsm_x4(ah[mi][0], ah[mi][1], ah[mi][2], ah[mi][3], base + aoff);
                ldsm_x4(al[mi][0], al[mi][1], al[mi][2], al[mi][3], base + G_AT + aoff);
            }
            uint32_t wh[2][4];
#pragma unroll
            for (int nj = 0; nj < 2; nj++) {
                uint32_t woff = (uint32_t)(lw_row + nj*16) * GSTRIDE + (ks*16 + lw_k8) * 2;
                ldsm_x4(wh[nj][0], wh[nj][1], wh[nj][2], wh[nj][3], base + 2*G_AT + woff);
            }
#pragma unroll
            for (int mi = 0; mi < 4; mi++)
#pragma unroll
                for (int nf = 0; nf < 4; nf++) {
                    const uint32_t* bh = &wh[nf >> 1][(nf & 1) * 2];
                    mma16816(acc[mi][nf], ah[mi], bh);
                    mma16816(acc[mi][nf], al[mi], bh);
                }
        }
        __syncthreads();
        if (kt + 2 < NKC) { LOAD_P(kt & 1, kt + 2); CP_COMMIT(); }
    }

    const int crow  = mbase + warp_m * 64 + (lane >> 2);
    const int ccol0 = nbase + warp_n * 32 + (lane & 3) * 2;
#pragma unroll
    for (int nf = 0; nf < 4; nf++) {
        float2 bv = *(const float2*)(bias + ccol0 + nf * 8);
#pragma unroll
        for (int mi = 0; mi < 4; mi++) {
            float* c = acc[mi][nf];
            *(float2*)(Fout + (size_t)(crow + mi*16)     * NE + ccol0 + nf*8) =
                make_float2(c[0] * 0.015625f + bv.x, c[1] * 0.015625f + bv.y);
            *(float2*)(Fout + (size_t)(crow + mi*16 + 8) * NE + ccol0 + nf*8) =
                make_float2(c[2] * 0.015625f + bv.x, c[3] * 0.015625f + bv.y);
        }
    }
#undef LOAD_P
}

// ---------------------------------------------------------------------------
// Flash attention, 1-term fp16 mma (S = Qh*Kh^T, O += Ph*Vh). Unchanged.
// ---------------------------------------------------------------------------
#define ARSTRIDE 144
#define ATILE    (64 * ARSTRIDE)       // 9216
#define ASTAGE   (2 * ATILE)           // 18432 : Kh|Vh
#define ASMEM2   (2 * ASTAGE)          // 36864

__global__ void __launch_bounds__(128, 3)
attn_tc()
{
    extern __shared__ char smem[];
    const int tid  = threadIdx.x;
    const int wid  = tid >> 5;
    const int lane = tid & 31;
    const int qt   = (int)gridDim.x - 1 - (int)blockIdx.x;   // heavy first
    const int bh   = blockIdx.y;
    const int b    = bh >> 4;
    const int h    = bh & 15;
    const size_t base = (size_t)b * TSEQ * NE + (size_t)h * DKH;
    const int qb   = qt * 64;
    const uint32_t smb = smem_u32(smem);

#pragma unroll
    for (int i = 0; i < 4; i++) {
        int idx = i * 128 + tid;
        int r = idx >> 3, c = idx & 7;
        *(uint4*)(smem + r * ARSTRIDE + c * 16) =
            *(const uint4*)(g_Qh + base + (size_t)(qb + r) * NE + c * 8);
    }
    __syncthreads();

    const int la_row = wid * 16 + (lane & 15);
    const int la_k8  = ((lane >> 4) & 1) * 8;
    uint32_t qh[4][4];
#pragma unroll
    for (int ks = 0; ks < 4; ks++) {
        uint32_t aoff = (uint32_t)la_row * ARSTRIDE + (ks * 16 + la_k8) * 2;
        ldsm_x4(qh[ks][0], qh[ks][1], qh[ks][2], qh[ks][3], smb + aoff);
    }
    __syncthreads();

    const int lw_row = (lane & 7) + ((lane >> 4) & 1) * 8;
    const int lw_k8  = ((lane >> 3) & 1) * 8;
    const int vt_row = (lane & 7) + ((lane >> 3) & 1) * 8;
    const int vt_cb  = ((lane >> 4) & 1) * 16;

    float m_r[2] = {-1e30f, -1e30f}, l_r[2] = {0.f, 0.f};
    float o[8][4];
#pragma unroll
    for (int nf = 0; nf < 8; nf++)
#pragma unroll
        for (int q = 0; q < 4; q++) o[nf][q] = 0.f;

    const __half* kvp[2] = { g_Kh, g_Vh };

#define LOAD_KV(buf, kt) do {                                                 \
        uint32_t sb_ = smb + (buf) * ASTAGE;                                  \
        int ktb_ = (kt) * 64;                                                 \
        _Pragma("unroll")                                                     \
        for (int i = 0; i < 8; i++) {                                         \
            int id_ = i * 128 + tid;                                          \
            int t2_ = id_ >> 9;                                               \
            int ix_ = id_ & 511;                                              \
            int r_ = ix_ >> 3, c_ = ix_ & 7;                                  \
            const char* src_ = (const char*)(kvp[t2_] + base +                \
                (size_t)(ktb_ + r_) * NE + c_ * 8);                           \
            CP_A16(sb_ + t2_ * ATILE + r_ * ARSTRIDE + c_ * 16, src_);        \
        }                                                                     \
    } while (0)

    const int nkt = qt + 1;
    LOAD_KV(0, 0); CP_COMMIT();
    if (nkt > 1) { LOAD_KV(1, 1); CP_COMMIT(); }

    for (int kt = 0; kt < nkt; kt++) {
        if (kt + 1 < nkt) CP_WAIT1(); else CP_WAIT0();
        __syncthreads();
        const uint32_t sb = smb + (kt & 1) * ASTAGE;

        float s[8][4];
#pragma unroll
        for (int nf = 0; nf < 8; nf++)
#pragma unroll
            for (int q = 0; q < 4; q++) s[nf][q] = 0.f;

#pragma unroll
        for (int ks = 0; ks < 4; ks++) {
            uint32_t kh[4][4];
#pragma unroll
            for (int nj = 0; nj < 4; nj++) {
                uint32_t woff = (uint32_t)(nj * 16 + lw_row) * ARSTRIDE + (ks * 16 + lw_k8) * 2;
                ldsm_x4(kh[nj][0], kh[nj][1], kh[nj][2], kh[nj][3], sb + woff);
            }
#pragma unroll
            for (int nf = 0; nf < 8; nf++)
                mma16816(s[nf], qh[ks], &kh[nf >> 1][(nf & 1) * 2]);
        }

        if (kt == nkt - 1) {
            const int rl0 = wid * 16 + (lane >> 2);
#pragma unroll
            for (int nf = 0; nf < 8; nf++) {
                int cl = nf * 8 + (lane & 3) * 2;
                if (cl     > rl0)     s[nf][0] = -1e30f;
                if (cl + 1 > rl0)     s[nf][1] = -1e30f;
                if (cl     > rl0 + 8) s[nf][2] = -1e30f;
                if (cl + 1 > rl0 + 8) s[nf][3] = -1e30f;
            }
        }

        float corr[2];
#pragma unroll
        for (int r = 0; r < 2; r++) {
            float mx = -1e30f;
#pragma unroll
            for (int nf = 0; nf < 8; nf++)
                mx = fmaxf(mx, fmaxf(s[nf][2*r], s[nf][2*r + 1]));
            mx = fmaxf(mx, __shfl_xor_sync(0xffffffffu, mx, 1));
            mx = fmaxf(mx, __shfl_xor_sync(0xffffffffu, mx, 2));
            float mnew = fmaxf(m_r[r], mx);
            corr[r] = __expf(m_r[r] - mnew);
            float ps = 0.f;
#pragma unroll
            for (int nf = 0; nf < 8; nf++) {
                float p0 = __expf(s[nf][2*r]     - mnew);
                float p1 = __expf(s[nf][2*r + 1] - mnew);
                s[nf][2*r] = p0; s[nf][2*r + 1] = p1;
                ps += p0 + p1;
            }
            ps += __shfl_xor_sync(0xffffffffu, ps, 1);
            ps += __shfl_xor_sync(0xffffffffu, ps, 2);
            l_r[r] = l_r[r] * corr[r] + ps;
            m_r[r] = mnew;
        }
#pragma unroll
        for (int nf = 0; nf < 8; nf++) {
            o[nf][0] *= corr[0]; o[nf][1] *= corr[0];
            o[nf][2] *= corr[1]; o[nf][3] *= corr[1];
        }

#pragma unroll
        for (int ks2 = 0; ks2 < 4; ks2++) {
            uint32_t pa_h[4];
            pa_h[0] = pack_h2(s[2*ks2][0],     s[2*ks2][1]);
            pa_h[1] = pack_h2(s[2*ks2][2],     s[2*ks2][3]);
            pa_h[2] = pack_h2(s[2*ks2 + 1][0], s[2*ks2 + 1][1]);
            pa_h[3] = pack_h2(s[2*ks2 + 1][2], s[2*ks2 + 1][3]);

            uint32_t vh[4][4];
#pragma unroll
            for (int df = 0; df < 4; df++) {
                uint32_t voff = (uint32_t)(ks2 * 16 + vt_row) * ARSTRIDE + df * 32 + vt_cb;
                ldsm_x4_t(vh[df][0], vh[df][1], vh[df][2], vh[df][3], sb + ATILE + voff);
            }
#pragma unroll
            for (int nf = 0; nf < 8; nf++)
                mma16816(o[nf], pa_h, &vh[nf >> 1][(nf & 1) * 2]);
        }
        __syncthreads();
        if (kt + 2 < nkt) { LOAD_KV(kt & 1, kt + 2); CP_COMMIT(); }
    }

    const float inv0 = 64.f / l_r[0];
    const float inv1 = 64.f / l_r[1];
    const int grow = qb + wid * 16 + (lane >> 2);
    const int d0 = (lane & 3) * 2;
#pragma unroll
    for (int nf = 0; nf < 8; nf++) {
        uint32_t h0, l0, h1, l1;
        split_h2(o[nf][0] * inv0, o[nf][1] * inv0, h0, l0);
        split_h2(o[nf][2] * inv1, o[nf][3] * inv1, h1, l1);
        size_t p0 = base + (size_t)grow * NE + nf * 8 + d0;
        size_t p1 = base + (size_t)(grow + 8) * NE + nf * 8 + d0;
        *(uint32_t*)(g_Yh + p0) = h0; *(uint32_t*)(g_Yl + p0) = l0;
        *(uint32_t*)(g_Yh + p1) = h1; *(uint32_t*)(g_Yl + p1) = l1;
    }
#undef LOAD_KV
}

// ---------------------------------------------------------------------------
extern "C" void kernel_launch(void* const* d_in, const int* in_sizes, int n_in,
                              void* d_out, int out_size)
{
    const float* x  = (const float*)d_in[0];
    const float* Wq = (const float*)d_in[1];
    const float* bq = (const float*)d_in[2];
    const float* Wk = (const float*)d_in[3];
    const float* bk = (const float*)d_in[4];
    const float* Wv = (const float*)d_in[5];
    const float* bv = (const float*)d_in[6];
    const float* Wo = (const float*)d_in[7];
    const float* bo = (const float*)d_in[8];
    float* out = (float*)d_out;

    __half *Xh, *WhB, *Qh, *Kh, *Vh, *Yh, *Yl;
    cudaGetSymbolAddress((void**)&Xh, g_Xh);
    cudaGetSymbolAddress((void**)&WhB, g_Wh);
    cudaGetSymbolAddress((void**)&Qh, g_Qh);
    cudaGetSymbolAddress((void**)&Kh, g_Kh);
    cudaGetSymbolAddress((void**)&Vh, g_Vh);
    cudaGetSymbolAddress((void**)&Yh, g_Yh);  cudaGetSymbolAddress((void**)&Yl, g_Yl);

    static bool attr_done = false;
    if (!attr_done) {
        cudaFuncSetAttribute(gemm_qkv,  cudaFuncAttributeMaxDynamicSharedMemorySize, QSMEM);
        cudaFuncSetAttribute(gemm_proj, cudaFuncAttributeMaxDynamicSharedMemorySize, PSMEM);
        attr_done = true;
    }

    // fused pre-pass: x -> Xh, weights -> Wh
    split_all<<<8192, 256>>>(x, Wq, Wk, Wv, Wo, Xh, WhB);

    // QKV projections (1-term, fp16 outputs, Q pre-scaled by 0.125)
    gemm_qkv<<<dim3(16, 32, 3), 128, QSMEM>>>(Xh, WhB, bq, bk, bv, Qh, Kh, Vh);
    // attention (1-term S and PV, Y = 64*O split fp16)
    attn_tc<<<dim3(32, 32), 128, ASMEM2>>>();
    // output projection (2-term, fp32 out, undoes the 64x)
    gemm_proj<<<dim3(16, 32, 1), 128, PSMEM>>>(Yh, Yl, WhB + 3*(size_t)NE*NE, bo, out);
}

// round 11
// speedup vs baseline: 2.1439x; 1.0032x over previous
#include <cuda_runtime.h>
#include <cuda_fp16.h>
#include <cstdint>
#include <math.h>

#define TSEQ 2048
#define NE   1024
#define NH   16
#define DKH  64
#define NB   2
#define MTOT (NB*TSEQ)   // 4096

// Scratch (allocation-free), fp16.
__device__ __half g_Xh[MTOT*NE];
__device__ __half g_Wh[4*NE*NE];                 // q,k,v,o (hi only)
__device__ __half g_Qh[MTOT*NE];                 // Q pre-scaled by 0.125
__device__ __half g_Kh[MTOT*NE];
__device__ __half g_Vh[MTOT*NE];
__device__ __half g_Yh[MTOT*NE], g_Yl[MTOT*NE]; // attention out, pre-scaled by 64

// ---------------------------------------------------------------------------
// Baseline-PTX tensor ops + cp.async (plain sm_103 target)
// ---------------------------------------------------------------------------
static __device__ __forceinline__ uint32_t smem_u32(const void* p) {
    uint32_t a;
    asm("{ .reg .u64 t; cvta.to.shared.u64 t, %1; cvt.u32.u64 %0, t; }" : "=r"(a) : "l"(p));
    return a;
}
static __device__ __forceinline__ void ldsm_x4(uint32_t& r0, uint32_t& r1,
                                               uint32_t& r2, uint32_t& r3, uint32_t a) {
    asm volatile("ldmatrix.sync.aligned.m8n8.x4.shared.b16 {%0,%1,%2,%3}, [%4];"
                 : "=r"(r0), "=r"(r1), "=r"(r2), "=r"(r3) : "r"(a));
}
static __device__ __forceinline__ void ldsm_x4_t(uint32_t& r0, uint32_t& r1,
                                                 uint32_t& r2, uint32_t& r3, uint32_t a) {
    asm volatile("ldmatrix.sync.aligned.m8n8.x4.trans.shared.b16 {%0,%1,%2,%3}, [%4];"
                 : "=r"(r0), "=r"(r1), "=r"(r2), "=r"(r3) : "r"(a));
}
static __device__ __forceinline__ void mma16816(float* c, const uint32_t* a, const uint32_t* b) {
    asm volatile("mma.sync.aligned.m16n8k16.row.col.f32.f16.f16.f32 "
                 "{%0,%1,%2,%3}, {%4,%5,%6,%7}, {%8,%9}, {%0,%1,%2,%3};"
                 : "+f"(c[0]), "+f"(c[1]), "+f"(c[2]), "+f"(c[3])
                 : "r"(a[0]), "r"(a[1]), "r"(a[2]), "r"(a[3]), "r"(b[0]), "r"(b[1]));
}
#define CP_A16(dst, src) asm volatile("cp.async.cg.shared.global [%0], [%1], 16;" :: "r"(dst), "l"(src))
#define CP_COMMIT()      asm volatile("cp.async.commit_group;" ::: "memory")
#define CP_WAIT0()       asm volatile("cp.async.wait_group 0;" ::: "memory")
#define CP_WAIT1()       asm volatile("cp.async.wait_group 1;" ::: "memory")

static __device__ __forceinline__ uint32_t pack_h2(float x, float y) {
    union { __half2 b; uint32_t u; } p;
    p.b.x = __float2half_rn(x); p.b.y = __float2half_rn(y);
    return p.u;
}
static __device__ __forceinline__ void split_h2(float x, float y, uint32_t& h, uint32_t& l) {
    __half hx = __float2half_rn(x), hy = __float2half_rn(y);
    union { __half2 b; uint32_t u; } ph, pl;
    ph.b.x = hx; ph.b.y = hy;
    pl.b.x = __float2half_rn(x - __half2float(hx));
    pl.b.y = __float2half_rn(y - __half2float(hy));
    h = ph.u; l = pl.u;
}

// ---------------------------------------------------------------------------
// Fused pre-pass: x -> Xh; Wq,k,v,o -> Wh. (hi-only everywhere)
// ---------------------------------------------------------------------------
__global__ void split_all(const float* __restrict__ x,
                          const float* __restrict__ Wq, const float* __restrict__ Wk,
                          const float* __restrict__ Wv, const float* __restrict__ Wo,
                          __half* __restrict__ Xh, __half* __restrict__ WhB)
{
    const int bx = blockIdx.x;
    if (bx < 4096) {
        size_t i = (size_t)bx * 1024 + threadIdx.x * 4;
        float4 v = *(const float4*)(x + i);
        *(uint2*)(Xh + i) = make_uint2(pack_h2(v.x, v.y), pack_h2(v.z, v.w));
    } else {
        const int r = bx - 4096;
        const int w = r >> 10;
        const float* ws = (w == 0) ? Wq : (w == 1) ? Wk : (w == 2) ? Wv : Wo;
        size_t j = (size_t)(r & 1023) * 1024 + threadIdx.x * 4;
        float4 v = *(const float4*)(ws + j);
        *(uint2*)(WhB + (size_t)w * NE * NE + j) =
            make_uint2(pack_h2(v.x, v.y), pack_h2(v.z, v.w));
    }
}

// ---------------------------------------------------------------------------
// Shared GEMM tiling constants. 128x64 CTA tile, 128 threads, kc=32,
// 2-stage cp.async ring, 3 CTAs/SM.
// ---------------------------------------------------------------------------
#define GSTRIDE 80
#define G_AT    (128 * GSTRIDE)          // 10240
#define G_WT    (64 * GSTRIDE)           // 5120
#define NKC     (NE / 32)                // 32

// ---- QKV GEMM: 1 term (Xh * Wh^T), fp16-hi output (z=0 scaled 0.125) ----
#define Q_STAGE (G_AT + G_WT)            // 15360 : Ah|Wh
#define QSMEM   (2 * Q_STAGE)            // 30720

__global__ void __launch_bounds__(128, 3)
gemm_qkv(const __half* __restrict__ Ah, const __half* __restrict__ WhB,
         const float* __restrict__ b0, const float* __restrict__ b1, const float* __restrict__ b2,
         __half* __restrict__ O0, __half* __restrict__ O1, __half* __restrict__ O2)
{
    extern __shared__ char smem[];
    const int tid  = threadIdx.x;
    const int wid  = tid >> 5;
    const int lane = tid & 31;
    const int z    = blockIdx.z;
    const __half* Wh = WhB + (size_t)z * NE * NE;
    const float* bias = (z == 0) ? b0 : (z == 1) ? b1 : b2;
    const int mbase = blockIdx.y * 128;
    const int nbase = blockIdx.x * 64;
    const uint32_t smb = smem_u32(smem);

    const int warp_m = wid >> 1;
    const int warp_n = wid & 1;
    const int la_row = warp_m * 64 + (lane & 15);
    const int la_k8  = ((lane >> 4) & 1) * 8;
    const int lw_row = warp_n * 32 + (lane & 7) + ((lane >> 4) & 1) * 8;
    const int lw_k8  = ((lane >> 3) & 1) * 8;

    const int lr = tid >> 2;       // 0..31
    const int lc = tid & 3;        // 0..3

    float acc[4][4][4];
#pragma unroll
    for (int mi = 0; mi < 4; mi++)
#pragma unroll
        for (int nf = 0; nf < 4; nf++)
#pragma unroll
            for (int q = 0; q < 4; q++) acc[mi][nf][q] = 0.f;

#define LOAD_Q(buf, kt) do {                                                  \
        uint32_t sb_ = smb + (buf) * Q_STAGE;                                 \
        int kcol_ = (kt) * 32 + lc * 8;                                       \
        _Pragma("unroll")                                                     \
        for (int i = 0; i < 4; i++) {                                         \
            int r_ = lr + 32 * i;                                             \
            CP_A16(sb_ + r_ * GSTRIDE + lc * 16,                              \
                   (const char*)(Ah + (size_t)(mbase + r_) * NE + kcol_));    \
        }                                                                     \
        _Pragma("unroll")                                                     \
        for (int i = 0; i < 2; i++) {                                         \
            int r_ = lr + 32 * i;                                             \
            CP_A16(sb_ + G_AT + r_ * GSTRIDE + lc * 16,                       \
                   (const char*)(Wh + (size_t)(nbase + r_) * NE + kcol_));    \
        }                                                                     \
    } while (0)

    LOAD_Q(0, 0); CP_COMMIT();
    LOAD_Q(1, 1); CP_COMMIT();

    for (int kt = 0; kt < NKC; kt++) {
        if (kt + 1 < NKC) CP_WAIT1(); else CP_WAIT0();
        __syncthreads();

        const uint32_t base = smb + (kt & 1) * Q_STAGE;
#pragma unroll
        for (int ks = 0; ks < 2; ks++) {
            uint32_t ah[4][4];
#pragma unroll
            for (int mi = 0; mi < 4; mi++) {
                uint32_t aoff = (uint32_t)(la_row + mi*16) * GSTRIDE + (ks*16 + la_k8) * 2;
                ldsm_x4(ah[mi][0], ah[mi][1], ah[mi][2], ah[mi][3], base + aoff);
            }
            uint32_t wh[2][4];
#pragma unroll
            for (int nj = 0; nj < 2; nj++) {
                uint32_t woff = (uint32_t)(lw_row + nj*16) * GSTRIDE + (ks*16 + lw_k8) * 2;
                ldsm_x4(wh[nj][0], wh[nj][1], wh[nj][2], wh[nj][3], base + G_AT + woff);
            }
#pragma unroll
            for (int mi = 0; mi < 4; mi++)
#pragma unroll
                for (int nf = 0; nf < 4; nf++)
                    mma16816(acc[mi][nf], ah[mi], &wh[nf >> 1][(nf & 1) * 2]);
        }
        __syncthreads();
        if (kt + 2 < NKC) { LOAD_Q(kt & 1, kt + 2); CP_COMMIT(); }
    }

    const int crow  = mbase + warp_m * 64 + (lane >> 2);
    const int ccol0 = nbase + warp_n * 32 + (lane & 3) * 2;
    __half* O = (z == 0) ? O0 : (z == 1) ? O1 : O2;
    const float scale = (z == 0) ? 0.125f : 1.0f;
#pragma unroll
    for (int nf = 0; nf < 4; nf++) {
        float2 bv = *(const float2*)(bias + ccol0 + nf * 8);
#pragma unroll
        for (int mi = 0; mi < 4; mi++) {
            float* c = acc[mi][nf];
            size_t o0 = (size_t)(crow + mi*16)     * NE + ccol0 + nf*8;
            size_t o1 = (size_t)(crow + mi*16 + 8) * NE + ccol0 + nf*8;
            *(uint32_t*)(O + o0) = pack_h2((c[0] + bv.x) * scale, (c[1] + bv.y) * scale);
            *(uint32_t*)(O + o1) = pack_h2((c[2] + bv.x) * scale, (c[3] + bv.y) * scale);
        }
    }
#undef LOAD_Q
}

// ---- Out-proj GEMM: 2 terms ((Yh+Yl) * Wh^T), fp32 out, undoes the 64x ----
#define P_STAGE (2*G_AT + G_WT)          // 25600 : Ah|Al|Wh
#define PSMEM   (2 * P_STAGE)            // 51200

__global__ void __launch_bounds__(128, 3)
gemm_proj(const __half* __restrict__ Ah, const __half* __restrict__ Al,
          const __half* __restrict__ Wh, const float* __restrict__ bias,
          float* __restrict__ Fout)
{
    extern __shared__ char smem[];
    const int tid  = threadIdx.x;
    const int wid  = tid >> 5;
    const int lane = tid & 31;
    const int mbase = blockIdx.y * 128;
    const int nbase = blockIdx.x * 64;
    const uint32_t smb = smem_u32(smem);

    const int warp_m = wid >> 1;
    const int warp_n = wid & 1;
    const int la_row = warp_m * 64 + (lane & 15);
    const int la_k8  = ((lane >> 4) & 1) * 8;
    const int lw_row = warp_n * 32 + (lane & 7) + ((lane >> 4) & 1) * 8;
    const int lw_k8  = ((lane >> 3) & 1) * 8;

    const int lr = tid >> 2;
    const int lc = tid & 3;

    float acc[4][4][4];
#pragma unroll
    for (int mi = 0; mi < 4; mi++)
#pragma unroll
        for (int nf = 0; nf < 4; nf++)
#pragma unroll
            for (int q = 0; q < 4; q++) acc[mi][nf][q] = 0.f;

#define LOAD_P(buf, kt) do {                                                  \
        uint32_t sb_ = smb + (buf) * P_STAGE;                                 \
        int kcol_ = (kt) * 32 + lc * 8;                                       \
        _Pragma("unroll")                                                     \
        for (int i = 0; i < 4; i++) {                                         \
            int r_ = lr + 32 * i;                                             \
            CP_A16(sb_ + r_ * GSTRIDE + lc * 16,                              \
                   (const char*)(Ah + (size_t)(mbase + r_) * NE + kcol_));    \
            CP_A16(sb_ + G_AT + r_ * GSTRIDE + lc * 16,                       \
                   (const char*)(Al + (size_t)(mbase + r_) * NE + kcol_));    \
        }                                                                     \
        _Pragma("unroll")                                                     \
        for (int i = 0; i < 2; i++) {                                         \
            int r_ = lr + 32 * i;                                             \
            CP_A16(sb_ + 2*G_AT + r_ * GSTRIDE + lc * 16,                     \
                   (const char*)(Wh + (size_t)(nbase + r_) * NE + kcol_));    \
        }                                                                     \
    } while (0)

    LOAD_P(0, 0); CP_COMMIT();
    LOAD_P(1, 1); CP_COMMIT();

    for (int kt = 0; kt < NKC; kt++) {
        if (kt + 1 < NKC) CP_WAIT1(); else CP_WAIT0();
        __syncthreads();

        const uint32_t base = smb + (kt & 1) * P_STAGE;
#pragma unroll
        for (int ks = 0; ks < 2; ks++) {
            uint32_t ah[4][4], al[4][4];
#pragma unroll
            for (int mi = 0; mi < 4; mi++) {
                uint32_t aoff = (uint32_t)(la_row + mi*16) * GSTRIDE + (ks*16 + la_k8) * 2;
                ldsm_x4(ah[mi][0], ah[mi][1], ah[mi][2], ah[mi][3], base + aoff);
                ldsm_x4(al[mi][0], al[mi][1], al[mi][2], al[mi][3], base + G_AT + aoff);
            }
            uint32_t wh[2][4];
#pragma unroll
            for (int nj = 0; nj < 2; nj++) {
                uint32_t woff = (uint32_t)(lw_row + nj*16) * GSTRIDE + (ks*16 + lw_k8) * 2;
                ldsm_x4(wh[nj][0], wh[nj][1], wh[nj][2], wh[nj][3], base + 2*G_AT + woff);
            }
#pragma unroll
            for (int mi = 0; mi < 4; mi++)
#pragma unroll
                for (int nf = 0; nf < 4; nf++) {
                    const uint32_t* bh = &wh[nf >> 1][(nf & 1) * 2];
                    mma16816(acc[mi][nf], ah[mi], bh);
                    mma16816(acc[mi][nf], al[mi], bh);
                }
        }
        __syncthreads();
        if (kt + 2 < NKC) { LOAD_P(kt & 1, kt + 2); CP_COMMIT(); }
    }

    const int crow  = mbase + warp_m * 64 + (lane >> 2);
    const int ccol0 = nbase + warp_n * 32 + (lane & 3) * 2;
#pragma unroll
    for (int nf = 0; nf < 4; nf++) {
        float2 bv = *(const float2*)(bias + ccol0 + nf * 8);
#pragma unroll
        for (int mi = 0; mi < 4; mi++) {
            float* c = acc[mi][nf];
            *(float2*)(Fout + (size_t)(crow + mi*16)     * NE + ccol0 + nf*8) =
                make_float2(c[0] * 0.015625f + bv.x, c[1] * 0.015625f + bv.y);
            *(float2*)(Fout + (size_t)(crow + mi*16 + 8) * NE + ccol0 + nf*8) =
                make_float2(c[2] * 0.015625f + bv.x, c[3] * 0.015625f + bv.y);
        }
    }
#undef LOAD_P
}

// ---------------------------------------------------------------------------
// Flash attention, 1-term fp16 mma (S = Qh*Kh^T, O += Ph*Vh). Unchanged.
// ---------------------------------------------------------------------------
#define ARSTRIDE 144
#define ATILE    (64 * ARSTRIDE)       // 9216
#define ASTAGE   (2 * ATILE)           // 18432 : Kh|Vh
#define ASMEM2   (2 * ASTAGE)          // 36864

__global__ void __launch_bounds__(128, 3)
attn_tc()
{
    extern __shared__ char smem[];
    const int tid  = threadIdx.x;
    const int wid  = tid >> 5;
    const int lane = tid & 31;
    const int qt   = (int)gridDim.x - 1 - (int)blockIdx.x;   // heavy first
    const int bh   = blockIdx.y;
    const int b    = bh >> 4;
    const int h    = bh & 15;
    const size_t base = (size_t)b * TSEQ * NE + (size_t)h * DKH;
    const int qb   = qt * 64;
    const uint32_t smb = smem_u32(smem);

#pragma unroll
    for (int i = 0; i < 4; i++) {
        int idx = i * 128 + tid;
        int r = idx >> 3, c = idx & 7;
        *(uint4*)(smem + r * ARSTRIDE + c * 16) =
            *(const uint4*)(g_Qh + base + (size_t)(qb + r) * NE + c * 8);
    }
    __syncthreads();

    const int la_row = wid * 16 + (lane & 15);
    const int la_k8  = ((lane >> 4) & 1) * 8;
    uint32_t qh[4][4];
#pragma unroll
    for (int ks = 0; ks < 4; ks++) {
        uint32_t aoff = (uint32_t)la_row * ARSTRIDE + (ks * 16 + la_k8) * 2;
        ldsm_x4(qh[ks][0], qh[ks][1], qh[ks][2], qh[ks][3], smb + aoff);
    }
    __syncthreads();

    const int lw_row = (lane & 7) + ((lane >> 4) & 1) * 8;
    const int lw_k8  = ((lane >> 3) & 1) * 8;
    const int vt_row = (lane & 7) + ((lane >> 3) & 1) * 8;
    const int vt_cb  = ((lane >> 4) & 1) * 16;

    float m_r[2] = {-1e30f, -1e30f}, l_r[2] = {0.f, 0.f};
    float o[8][4];
#pragma unroll
    for (int nf = 0; nf < 8; nf++)
#pragma unroll
        for (int q = 0; q < 4; q++) o[nf][q] = 0.f;

    const __half* kvp[2] = { g_Kh, g_Vh };

#define LOAD_KV(buf, kt) do {                                                 \
        uint32_t sb_ = smb + (buf) * ASTAGE;                                  \
        int ktb_ = (kt) * 64;                                                 \
        _Pragma("unroll")                                                     \
        for (int i = 0; i < 8; i++) {                                         \
            int id_ = i * 128 + tid;                                          \
            int t2_ = id_ >> 9;                                               \
            int ix_ = id_ & 511;                                              \
            int r_ = ix_ >> 3, c_ = ix_ & 7;                                  \
            const char* src_ = (const char*)(kvp[t2_] + base +                \
                (size_t)(ktb_ + r_) * NE + c_ * 8);                           \
            CP_A16(sb_ + t2_ * ATILE + r_ * ARSTRIDE + c_ * 16, src_);        \
        }                                                                     \
    } while (0)

    const int nkt = qt + 1;
    LOAD_KV(0, 0); CP_COMMIT();
    if (nkt > 1) { LOAD_KV(1, 1); CP_COMMIT(); }

    for (int kt = 0; kt < nkt; kt++) {
        if (kt + 1 < nkt) CP_WAIT1(); else CP_WAIT0();
        __syncthreads();
        const uint32_t sb = smb + (kt & 1) * ASTAGE;

        float s[8][4];
#pragma unroll
        for (int nf = 0; nf < 8; nf++)
#pragma unroll
            for (int q = 0; q < 4; q++) s[nf][q] = 0.f;

#pragma unroll
        for (int ks = 0; ks < 4; ks++) {
            uint32_t kh[4][4];
#pragma unroll
            for (int nj = 0; nj < 4; nj++) {
                uint32_t woff = (uint32_t)(nj * 16 + lw_row) * ARSTRIDE + (ks * 16 + lw_k8) * 2;
                ldsm_x4(kh[nj][0], kh[nj][1], kh[nj][2], kh[nj][3], sb + woff);
            }
#pragma unroll
            for (int nf = 0; nf < 8; nf++)
                mma16816(s[nf], qh[ks], &kh[nf >> 1][(nf & 1) * 2]);
        }

        if (kt == nkt - 1) {
            const int rl0 = wid * 16 + (lane >> 2);
#pragma unroll
            for (int nf = 0; nf < 8; nf++) {
                int cl = nf * 8 + (lane & 3) * 2;
                if (cl     > rl0)     s[nf][0] = -1e30f;
                if (cl + 1 > rl0)     s[nf][1] = -1e30f;
                if (cl     > rl0 + 8) s[nf][2] = -1e30f;
                if (cl + 1 > rl0 + 8) s[nf][3] = -1e30f;
            }
        }

        float corr[2];
#pragma unroll
        for (int r = 0; r < 2; r++) {
            float mx = -1e30f;
#pragma unroll
            for (int nf = 0; nf < 8; nf++)
                mx = fmaxf(mx, fmaxf(s[nf][2*r], s[nf][2*r + 1]));
            mx = fmaxf(mx, __shfl_xor_sync(0xffffffffu, mx, 1));
            mx = fmaxf(mx, __shfl_xor_sync(0xffffffffu, mx, 2));
            float mnew = fmaxf(m_r[r], mx);
            corr[r] = __expf(m_r[r] - mnew);
            float ps = 0.f;
#pragma unroll
            for (int nf = 0; nf < 8; nf++) {
                float p0 = __expf(s[nf][2*r]     - mnew);
                float p1 = __expf(s[nf][2*r + 1] - mnew);
                s[nf][2*r] = p0; s[nf][2*r + 1] = p1;
                ps += p0 + p1;
            }
            ps += __shfl_xor_sync(0xffffffffu, ps, 1);
            ps += __shfl_xor_sync(0xffffffffu, ps, 2);
            l_r[r] = l_r[r] * corr[r] + ps;
            m_r[r] = mnew;
        }
#pragma unroll
        for (int nf = 0; nf < 8; nf++) {
            o[nf][0] *= corr[0]; o[nf][1] *= corr[0];
            o[nf][2] *= corr[1]; o[nf][3] *= corr[1];
        }

#pragma unroll
        for (int ks2 = 0; ks2 < 4; ks2++) {
            uint32_t pa_h[4];
            pa_h[0] = pack_h2(s[2*ks2][0],     s[2*ks2][1]);
            pa_h[1] = pack_h2(s[2*ks2][2],     s[2*ks2][3]);
            pa_h[2] = pack_h2(s[2*ks2 + 1][0], s[2*ks2 + 1][1]);
            pa_h[3] = pack_h2(s[2*ks2 + 1][2], s[2*ks2 + 1][3]);

            uint32_t vh[4][4];
#pragma unroll
            for (int df = 0; df < 4; df++) {
                uint32_t voff = (uint32_t)(ks2 * 16 + vt_row) * ARSTRIDE + df * 32 + vt_cb;
                ldsm_x4_t(vh[df][0], vh[df][1], vh[df][2], vh[df][3], sb + ATILE + voff);
            }
#pragma unroll
            for (int nf = 0; nf < 8; nf++)
                mma16816(o[nf], pa_h, &vh[nf >> 1][(nf & 1) * 2]);
        }
        __syncthreads();
        if (kt + 2 < nkt) { LOAD_KV(kt & 1, kt + 2); CP_COMMIT(); }
    }

    const float inv0 = 64.f / l_r[0];
    const float inv1 = 64.f / l_r[1];
    const int grow = qb + wid * 16 + (lane >> 2);
    const int d0 = (lane & 3) * 2;
#pragma unroll
    for (int nf = 0; nf < 8; nf++) {
        uint32_t h0, l0, h1, l1;
        split_h2(o[nf][0] * inv0, o[nf][1] * inv0, h0, l0);
        split_h2(o[nf][2] * inv1, o[nf][3] * inv1, h1, l1);
        size_t p0 = base + (size_t)grow * NE + nf * 8 + d0;
        size_t p1 = base + (size_t)(grow + 8) * NE + nf * 8 + d0;
        *(uint32_t*)(g_Yh + p0) = h0; *(uint32_t*)(g_Yl + p0) = l0;
        *(uint32_t*)(g_Yh + p1) = h1; *(uint32_t*)(g_Yl + p1) = l1;
    }
#undef LOAD_KV
}

// ---------------------------------------------------------------------------
extern "C" void kernel_launch(void* const* d_in, const int* in_sizes, int n_in,
                              void* d_out, int out_size)
{
    const float* x  = (const float*)d_in[0];
    const float* Wq = (const float*)d_in[1];
    const float* bq = (const float*)d_in[2];
    const float* Wk = (const float*)d_in[3];
    const float* bk = (const float*)d_in[4];
    const float* Wv = (const float*)d_in[5];
    const float* bv = (const float*)d_in[6];
    const float* Wo = (const float*)d_in[7];
    const float* bo = (const float*)d_in[8];
    float* out = (float*)d_out;

    __half *Xh, *WhB, *Qh, *Kh, *Vh, *Yh, *Yl;
    cudaGetSymbolAddress((void**)&Xh, g_Xh);
    cudaGetSymbolAddress((void**)&WhB, g_Wh);
    cudaGetSymbolAddress((void**)&Qh, g_Qh);
    cudaGetSymbolAddress((void**)&Kh, g_Kh);
    cudaGetSymbolAddress((void**)&Vh, g_Vh);
    cudaGetSymbolAddress((void**)&Yh, g_Yh);  cudaGetSymbolAddress((void**)&Yl, g_Yl);

    static bool attr_done = false;
    if (!attr_done) {
        cudaFuncSetAttribute(gemm_qkv,  cudaFuncAttributeMaxDynamicSharedMemorySize, QSMEM);
        cudaFuncSetAttribute(gemm_proj, cudaFuncAttributeMaxDynamicSharedMemorySize, PSMEM);
        attr_done = true;
    }

    // fused pre-pass: x -> Xh, weights -> Wh
    split_all<<<8192, 256>>>(x, Wq, Wk, Wv, Wo, Xh, WhB);

    // QKV projections (1-term, fp16 outputs, Q pre-scaled by 0.125)
    gemm_qkv<<<dim3(16, 32, 3), 128, QSMEM>>>(Xh, WhB, bq, bk, bv, Qh, Kh, Vh);
    // attention (1-term S and PV, Y = 64*O split fp16)
    attn_tc<<<dim3(32, 32), 128, ASMEM2>>>();
    // output projection (2-term, fp32 out, undoes the 64x)
    gemm_proj<<<dim3(16, 32, 1), 128, PSMEM>>>(Yh, Yl, WhB + 3*(size_t)NE*NE, bo, out);
}

// round 12
// speedup vs baseline: 2.6159x; 1.2201x over previous
#include <cuda_runtime.h>
#include <cuda_fp16.h>
#include <cstdint>
#include <math.h>

#define TSEQ 2048
#define NE   1024
#define NH   16
#define DKH  64
#define NB   2
#define MTOT (NB*TSEQ)   // 4096

// Scratch (allocation-free), fp16.
__device__ __half g_Xh[MTOT*NE];
__device__ __half g_Wh[4*NE*NE];    // q,k,v,o
__device__ __half g_Qh[MTOT*NE];    // Q pre-scaled by 0.125
__device__ __half g_Kh[MTOT*NE];
__device__ __half g_Vh[MTOT*NE];
__device__ __half g_Yh[MTOT*NE];    // attention out, pre-scaled by 64

// ---------------------------------------------------------------------------
static __device__ __forceinline__ uint32_t smem_u32(const void* p) {
    uint32_t a;
    asm("{ .reg .u64 t; cvta.to.shared.u64 t, %1; cvt.u32.u64 %0, t; }" : "=r"(a) : "l"(p));
    return a;
}
static __device__ __forceinline__ void ldsm_x4(uint32_t& r0, uint32_t& r1,
                                               uint32_t& r2, uint32_t& r3, uint32_t a) {
    asm volatile("ldmatrix.sync.aligned.m8n8.x4.shared.b16 {%0,%1,%2,%3}, [%4];"
                 : "=r"(r0), "=r"(r1), "=r"(r2), "=r"(r3) : "r"(a));
}
static __device__ __forceinline__ void ldsm_x4_t(uint32_t& r0, uint32_t& r1,
                                                 uint32_t& r2, uint32_t& r3, uint32_t a) {
    asm volatile("ldmatrix.sync.aligned.m8n8.x4.trans.shared.b16 {%0,%1,%2,%3}, [%4];"
                 : "=r"(r0), "=r"(r1), "=r"(r2), "=r"(r3) : "r"(a));
}
static __device__ __forceinline__ void mma16816(float* c, const uint32_t* a, const uint32_t* b) {
    asm volatile("mma.sync.aligned.m16n8k16.row.col.f32.f16.f16.f32 "
                 "{%0,%1,%2,%3}, {%4,%5,%6,%7}, {%8,%9}, {%0,%1,%2,%3};"
                 : "+f"(c[0]), "+f"(c[1]), "+f"(c[2]), "+f"(c[3])
                 : "r"(a[0]), "r"(a[1]), "r"(a[2]), "r"(a[3]), "r"(b[0]), "r"(b[1]));
}
#define CP_A16(dst, src) asm volatile("cp.async.cg.shared.global [%0], [%1], 16;" :: "r"(dst), "l"(src))
#define CP_COMMIT()      asm volatile("cp.async.commit_group;" ::: "memory")
#define CP_WAIT0()       asm volatile("cp.async.wait_group 0;" ::: "memory")
#define CP_WAIT1()       asm volatile("cp.async.wait_group 1;" ::: "memory")

static __device__ __forceinline__ uint32_t pack_h2(float x, float y) {
    union { __half2 b; uint32_t u; } p;
    p.b.x = __float2half_rn(x); p.b.y = __float2half_rn(y);
    return p.u;
}

// ---------------------------------------------------------------------------
// Fused pre-pass: x -> Xh; Wq,k,v,o -> Wh.
// ---------------------------------------------------------------------------
__global__ void split_all(const float* __restrict__ x,
                          const float* __restrict__ Wq, const float* __restrict__ Wk,
                          const float* __restrict__ Wv, const float* __restrict__ Wo,
                          __half* __restrict__ Xh, __half* __restrict__ WhB)
{
    const int bx = blockIdx.x;
    if (bx < 4096) {
        size_t i = (size_t)bx * 1024 + threadIdx.x * 4;
        float4 v = *(const float4*)(x + i);
        *(uint2*)(Xh + i) = make_uint2(pack_h2(v.x, v.y), pack_h2(v.z, v.w));
    } else {
        const int r = bx - 4096;
        const int w = r >> 10;
        const float* ws = (w == 0) ? Wq : (w == 1) ? Wk : (w == 2) ? Wv : Wo;
        size_t j = (size_t)(r & 1023) * 1024 + threadIdx.x * 4;
        float4 v = *(const float4*)(ws + j);
        *(uint2*)(WhB + (size_t)w * NE * NE + j) =
            make_uint2(pack_h2(v.x, v.y), pack_h2(v.z, v.w));
    }
}

// ---------------------------------------------------------------------------
// GEMM: C = A * Wh^T (1 term). CTA 128x128, 128 threads, warp tile 64x64
// (2x2 warps), kc=32, 2-stage cp.async ring, 2 CTAs/SM.
// Per k-slice: 8 ldsm feed 32 MMAs (ratio 4.0).
// MODE 0: fp16 out, scale (z==0 ? 0.125 : 1). MODE 1: fp32 out, *1/64 + bias.
// ---------------------------------------------------------------------------
#define GSTRIDE 80
#define G_T     (128 * GSTRIDE)          // 10240 per tile (A or W)
#define G_STAGE (2 * G_T)                // 20480 : A|W
#define GSMEM   (2 * G_STAGE)            // 40960
#define NKC     (NE / 32)                // 32

template<int MODE>
__global__ void __launch_bounds__(128, 2)
gemm64(const __half* __restrict__ Ah, const __half* __restrict__ WhB,
       const float* __restrict__ b0, const float* __restrict__ b1, const float* __restrict__ b2,
       __half* __restrict__ O0, __half* __restrict__ O1, __half* __restrict__ O2,
       float* __restrict__ Fout)
{
    extern __shared__ char smem[];
    const int tid  = threadIdx.x;
    const int wid  = tid >> 5;
    const int lane = tid & 31;
    const int z    = blockIdx.z;
    const __half* Wh = WhB + (size_t)z * NE * NE;
    const float* bias = (z == 0) ? b0 : (z == 1) ? b1 : b2;
    const int mbase = blockIdx.y * 128;
    const int nbase = blockIdx.x * 128;
    const uint32_t smb = smem_u32(smem);

    const int warp_m = wid >> 1;        // 0..1 -> 64 rows
    const int warp_n = wid & 1;         // 0..1 -> 64 cols
    const int la_row = warp_m * 64 + (lane & 15);
    const int la_k8  = ((lane >> 4) & 1) * 8;
    const int lw_row = warp_n * 64 + (lane & 7) + ((lane >> 4) & 1) * 8;
    const int lw_k8  = ((lane >> 3) & 1) * 8;

    const int lr = tid >> 2;       // 0..31
    const int lc = tid & 3;        // 0..3

    float acc[4][8][4];
#pragma unroll
    for (int mi = 0; mi < 4; mi++)
#pragma unroll
        for (int nf = 0; nf < 8; nf++)
#pragma unroll
            for (int q = 0; q < 4; q++) acc[mi][nf][q] = 0.f;

#define LOAD_G(buf, kt) do {                                                  \
        uint32_t sb_ = smb + (buf) * G_STAGE;                                 \
        int kcol_ = (kt) * 32 + lc * 8;                                       \
        _Pragma("unroll")                                                     \
        for (int i = 0; i < 4; i++) {                                         \
            int r_ = lr + 32 * i;                                             \
            CP_A16(sb_ + r_ * GSTRIDE + lc * 16,                              \
                   (const char*)(Ah + (size_t)(mbase + r_) * NE + kcol_));    \
            CP_A16(sb_ + G_T + r_ * GSTRIDE + lc * 16,                        \
                   (const char*)(Wh + (size_t)(nbase + r_) * NE + kcol_));    \
        }                                                                     \
    } while (0)

    LOAD_G(0, 0); CP_COMMIT();
    LOAD_G(1, 1); CP_COMMIT();

    for (int kt = 0; kt < NKC; kt++) {
        if (kt + 1 < NKC) CP_WAIT1(); else CP_WAIT0();
        __syncthreads();

        const uint32_t base = smb + (kt & 1) * G_STAGE;
#pragma unroll
        for (int ks = 0; ks < 2; ks++) {
            uint32_t ah[4][4];
#pragma unroll
            for (int mi = 0; mi < 4; mi++) {
                uint32_t aoff = (uint32_t)(la_row + mi*16) * GSTRIDE + (ks*16 + la_k8) * 2;
                ldsm_x4(ah[mi][0], ah[mi][1], ah[mi][2], ah[mi][3], base + aoff);
            }
            uint32_t wh[4][4];
#pragma unroll
            for (int nj = 0; nj < 4; nj++) {
                uint32_t woff = (uint32_t)(lw_row + nj*16) * GSTRIDE + (ks*16 + lw_k8) * 2;
                ldsm_x4(wh[nj][0], wh[nj][1], wh[nj][2], wh[nj][3], base + G_T + woff);
            }
#pragma unroll
            for (int mi = 0; mi < 4; mi++)
#pragma unroll
                for (int nf = 0; nf < 8; nf++)
                    mma16816(acc[mi][nf], ah[mi], &wh[nf >> 1][(nf & 1) * 2]);
        }
        __syncthreads();
        if (kt + 2 < NKC) { LOAD_G(kt & 1, kt + 2); CP_COMMIT(); }
    }

    const int crow  = mbase + warp_m * 64 + (lane >> 2);
    const int ccol0 = nbase + warp_n * 64 + (lane & 3) * 2;
    if constexpr (MODE == 0) {
        __half* O = (z == 0) ? O0 : (z == 1) ? O1 : O2;
        const float scale = (z == 0) ? 0.125f : 1.0f;
#pragma unroll
        for (int nf = 0; nf < 8; nf++) {
            float2 bv = *(const float2*)(bias + ccol0 + nf * 8);
#pragma unroll
            for (int mi = 0; mi < 4; mi++) {
                float* c = acc[mi][nf];
                size_t o0 = (size_t)(crow + mi*16)     * NE + ccol0 + nf*8;
                size_t o1 = (size_t)(crow + mi*16 + 8) * NE + ccol0 + nf*8;
                *(uint32_t*)(O + o0) = pack_h2((c[0] + bv.x) * scale, (c[1] + bv.y) * scale);
                *(uint32_t*)(O + o1) = pack_h2((c[2] + bv.x) * scale, (c[3] + bv.y) * scale);
            }
        }
    } else {
#pragma unroll
        for (int nf = 0; nf < 8; nf++) {
            float2 bv = *(const float2*)(bias + ccol0 + nf * 8);
#pragma unroll
            for (int mi = 0; mi < 4; mi++) {
                float* c = acc[mi][nf];
                *(float2*)(Fout + (size_t)(crow + mi*16)     * NE + ccol0 + nf*8) =
                    make_float2(c[0] * 0.015625f + bv.x, c[1] * 0.015625f + bv.y);
                *(float2*)(Fout + (size_t)(crow + mi*16 + 8) * NE + ccol0 + nf*8) =
                    make_float2(c[2] * 0.015625f + bv.x, c[3] * 0.015625f + bv.y);
            }
        }
    }
#undef LOAD_G
}

// ---------------------------------------------------------------------------
// Flash attention, 1-term fp16 mma. Unchanged except Yh-only epilogue.
// ---------------------------------------------------------------------------
#define ARSTRIDE 144
#define ATILE    (64 * ARSTRIDE)       // 9216
#define ASTAGE   (2 * ATILE)           // 18432 : Kh|Vh
#define ASMEM2   (2 * ASTAGE)          // 36864

__global__ void __launch_bounds__(128, 3)
attn_tc()
{
    extern __shared__ char smem[];
    const int tid  = threadIdx.x;
    const int wid  = tid >> 5;
    const int lane = tid & 31;
    const int qt   = (int)gridDim.x - 1 - (int)blockIdx.x;   // heavy first
    const int bh   = blockIdx.y;
    const int b    = bh >> 4;
    const int h    = bh & 15;
    const size_t base = (size_t)b * TSEQ * NE + (size_t)h * DKH;
    const int qb   = qt * 64;
    const uint32_t smb = smem_u32(smem);

#pragma unroll
    for (int i = 0; i < 4; i++) {
        int idx = i * 128 + tid;
        int r = idx >> 3, c = idx & 7;
        *(uint4*)(smem + r * ARSTRIDE + c * 16) =
            *(const uint4*)(g_Qh + base + (size_t)(qb + r) * NE + c * 8);
    }
    __syncthreads();

    const int la_row = wid * 16 + (lane & 15);
    const int la_k8  = ((lane >> 4) & 1) * 8;
    uint32_t qh[4][4];
#pragma unroll
    for (int ks = 0; ks < 4; ks++) {
        uint32_t aoff = (uint32_t)la_row * ARSTRIDE + (ks * 16 + la_k8) * 2;
        ldsm_x4(qh[ks][0], qh[ks][1], qh[ks][2], qh[ks][3], smb + aoff);
    }
    __syncthreads();

    const int lw_row = (lane & 7) + ((lane >> 4) & 1) * 8;
    const int lw_k8  = ((lane >> 3) & 1) * 8;
    const int vt_row = (lane & 7) + ((lane >> 3) & 1) * 8;
    const int vt_cb  = ((lane >> 4) & 1) * 16;

    float m_r[2] = {-1e30f, -1e30f}, l_r[2] = {0.f, 0.f};
    float o[8][4];
#pragma unroll
    for (int nf = 0; nf < 8; nf++)
#pragma unroll
        for (int q = 0; q < 4; q++) o[nf][q] = 0.f;

    const __half* kvp[2] = { g_Kh, g_Vh };

#define LOAD_KV(buf, kt) do {                                                 \
        uint32_t sb_ = smb + (buf) * ASTAGE;                                  \
        int ktb_ = (kt) * 64;                                                 \
        _Pragma("unroll")                                                     \
        for (int i = 0; i < 8; i++) {                                         \
            int id_ = i * 128 + tid;                                          \
            int t2_ = id_ >> 9;                                               \
            int ix_ = id_ & 511;                                              \
            int r_ = ix_ >> 3, c_ = ix_ & 7;                                  \
            const char* src_ = (const char*)(kvp[t2_] + base +                \
                (size_t)(ktb_ + r_) * NE + c_ * 8);                           \
            CP_A16(sb_ + t2_ * ATILE + r_ * ARSTRIDE + c_ * 16, src_);        \
        }                                                                     \
    } while (0)

    const int nkt = qt + 1;
    LOAD_KV(0, 0); CP_COMMIT();
    if (nkt > 1) { LOAD_KV(1, 1); CP_COMMIT(); }

    for (int kt = 0; kt < nkt; kt++) {
        if (kt + 1 < nkt) CP_WAIT1(); else CP_WAIT0();
        __syncthreads();
        const uint32_t sb = smb + (kt & 1) * ASTAGE;

        float s[8][4];
#pragma unroll
        for (int nf = 0; nf < 8; nf++)
#pragma unroll
            for (int q = 0; q < 4; q++) s[nf][q] = 0.f;

#pragma unroll
        for (int ks = 0; ks < 4; ks++) {
            uint32_t kh[4][4];
#pragma unroll
            for (int nj = 0; nj < 4; nj++) {
                uint32_t woff = (uint32_t)(nj * 16 + lw_row) * ARSTRIDE + (ks * 16 + lw_k8) * 2;
                ldsm_x4(kh[nj][0], kh[nj][1], kh[nj][2], kh[nj][3], sb + woff);
            }
#pragma unroll
            for (int nf = 0; nf < 8; nf++)
                mma16816(s[nf], qh[ks], &kh[nf >> 1][(nf & 1) * 2]);
        }

        if (kt == nkt - 1) {
            const int rl0 = wid * 16 + (lane >> 2);
#pragma unroll
            for (int nf = 0; nf < 8; nf++) {
                int cl = nf * 8 + (lane & 3) * 2;
                if (cl     > rl0)     s[nf][0] = -1e30f;
                if (cl + 1 > rl0)     s[nf][1] = -1e30f;
                if (cl     > rl0 + 8) s[nf][2] = -1e30f;
                if (cl + 1 > rl0 + 8) s[nf][3] = -1e30f;
            }
        }

        float corr[2];
#pragma unroll
        for (int r = 0; r < 2; r++) {
            float mx = -1e30f;
#pragma unroll
            for (int nf = 0; nf < 8; nf++)
                mx = fmaxf(mx, fmaxf(s[nf][2*r], s[nf][2*r + 1]));
            mx = fmaxf(mx, __shfl_xor_sync(0xffffffffu, mx, 1));
            mx = fmaxf(mx, __shfl_xor_sync(0xffffffffu, mx, 2));
            float mnew = fmaxf(m_r[r], mx);
            corr[r] = __expf(m_r[r] - mnew);
            float ps = 0.f;
#pragma unroll
            for (int nf = 0; nf < 8; nf++) {
                float p0 = __expf(s[nf][2*r]     - mnew);
                float p1 = __expf(s[nf][2*r + 1] - mnew);
                s[nf][2*r] = p0; s[nf][2*r + 1] = p1;
                ps += p0 + p1;
            }
            ps += __shfl_xor_sync(0xffffffffu, ps, 1);
            ps += __shfl_xor_sync(0xffffffffu, ps, 2);
            l_r[r] = l_r[r] * corr[r] + ps;
            m_r[r] = mnew;
        }
#pragma unroll
        for (int nf = 0; nf < 8; nf++) {
            o[nf][0] *= corr[0]; o[nf][1] *= corr[0];
            o[nf][2] *= corr[1]; o[nf][3] *= corr[1];
        }

#pragma unroll
        for (int ks2 = 0; ks2 < 4; ks2++) {
            uint32_t pa_h[4];
            pa_h[0] = pack_h2(s[2*ks2][0],     s[2*ks2][1]);
            pa_h[1] = pack_h2(s[2*ks2][2],     s[2*ks2][3]);
            pa_h[2] = pack_h2(s[2*ks2 + 1][0], s[2*ks2 + 1][1]);
            pa_h[3] = pack_h2(s[2*ks2 + 1][2], s[2*ks2 + 1][3]);

            uint32_t vh[4][4];
#pragma unroll
            for (int df = 0; df < 4; df++) {
                uint32_t voff = (uint32_t)(ks2 * 16 + vt_row) * ARSTRIDE + df * 32 + vt_cb;
                ldsm_x4_t(vh[df][0], vh[df][1], vh[df][2], vh[df][3], sb + ATILE + voff);
            }
#pragma unroll
            for (int nf = 0; nf < 8; nf++)
                mma16816(o[nf], pa_h, &vh[nf >> 1][(nf & 1) * 2]);
        }
        __syncthreads();
        if (kt + 2 < nkt) { LOAD_KV(kt & 1, kt + 2); CP_COMMIT(); }
    }

    // normalize, scale by 64, store Yh
    const float inv0 = 64.f / l_r[0];
    const float inv1 = 64.f / l_r[1];
    const int grow = qb + wid * 16 + (lane >> 2);
    const int d0 = (lane & 3) * 2;
#pragma unroll
    for (int nf = 0; nf < 8; nf++) {
        size_t p0 = base + (size_t)grow * NE + nf * 8 + d0;
        size_t p1 = base + (size_t)(grow + 8) * NE + nf * 8 + d0;
        *(uint32_t*)(g_Yh + p0) = pack_h2(o[nf][0] * inv0, o[nf][1] * inv0);
        *(uint32_t*)(g_Yh + p1) = pack_h2(o[nf][2] * inv1, o[nf][3] * inv1);
    }
#undef LOAD_KV
}

// ---------------------------------------------------------------------------
extern "C" void kernel_launch(void* const* d_in, const int* in_sizes, int n_in,
                              void* d_out, int out_size)
{
    const float* x  = (const float*)d_in[0];
    const float* Wq = (const float*)d_in[1];
    const float* bq = (const float*)d_in[2];
    const float* Wk = (const float*)d_in[3];
    const float* bk = (const float*)d_in[4];
    const float* Wv = (const float*)d_in[5];
    const float* bv = (const float*)d_in[6];
    const float* Wo = (const float*)d_in[7];
    const float* bo = (const float*)d_in[8];
    float* out = (float*)d_out;

    __half *Xh, *WhB, *Qh, *Kh, *Vh, *Yh;
    cudaGetSymbolAddress((void**)&Xh, g_Xh);
    cudaGetSymbolAddress((void**)&WhB, g_Wh);
    cudaGetSymbolAddress((void**)&Qh, g_Qh);
    cudaGetSymbolAddress((void**)&Kh, g_Kh);
    cudaGetSymbolAddress((void**)&Vh, g_Vh);
    cudaGetSymbolAddress((void**)&Yh, g_Yh);

    static bool attr_done = false;
    if (!attr_done) {
        cudaFuncSetAttribute(gemm64<0>, cudaFuncAttributeMaxDynamicSharedMemorySize, GSMEM);
        cudaFuncSetAttribute(gemm64<1>, cudaFuncAttributeMaxDynamicSharedMemorySize, GSMEM);
        attr_done = true;
    }

    // fused pre-pass: x -> Xh, weights -> Wh
    split_all<<<8192, 256>>>(x, Wq, Wk, Wv, Wo, Xh, WhB);

    // QKV projections (1-term, fp16 outputs, Q pre-scaled by 0.125)
    gemm64<0><<<dim3(8, 32, 3), 128, GSMEM>>>(Xh, WhB, bq, bk, bv, Qh, Kh, Vh, nullptr);
    // attention (1-term S and PV, Y = 64*O fp16)
    attn_tc<<<dim3(32, 32), 128, ASMEM2>>>();
    // output projection (1-term, fp32 out, undoes the 64x)
    gemm64<1><<<dim3(8, 32, 1), 128, GSMEM>>>(Yh, WhB + 3*(size_t)NE*NE, bo, bo, bo,
                                              nullptr, nullptr, nullptr, out);
}